// round 1
// baseline (speedup 1.0000x reference)
#include <cuda_runtime.h>
#include <math.h>

// ---------------- problem constants ----------------
#define BB    8
#define NTOK  1025
#define SP    1024      // spatial tokens (32x32)
#define FHW   32
#define DIMC  768
#define NKV   1536
#define HEADS 12
#define DH    64
#define NROT  32

// ---------------- scratch (static device arrays; allocation-free) ----------
__device__ float g_xn[BB*NTOK*DIMC];   // layernormed x
__device__ float g_dw[BB*SP*DIMC];     // depthwise conv out (b, tok, c)
__device__ float g_pw[BB*SP*DIMC];     // pointwise conv out (b, tok, c)
__device__ float g_kv[BB*NTOK*NKV];    // kv gemm out
__device__ float g_q [BB*NTOK*DIMC];   // q after rope (b, n, h*64+d)
__device__ float g_k [BB*NTOK*DIMC];
__device__ float g_v [BB*NTOK*DIMC];
__device__ float g_ao[BB*NTOK*DIMC];   // attention output

// ---------------- layernorm ----------------
__global__ void ln_kernel(const float* __restrict__ x,
                          const float* __restrict__ gamma,
                          const float* __restrict__ beta) {
    int row = blockIdx.x;               // 0..8199
    int t = threadIdx.x;                // 256 threads
    const float* xr = x + (size_t)row * DIMC;

    float v0 = xr[t], v1 = xr[t + 256], v2 = xr[t + 512];
    float s  = v0 + v1 + v2;
    float s2 = v0*v0 + v1*v1 + v2*v2;

    // block reduce (s, s2)
    int lane = t & 31, w = t >> 5;
    #pragma unroll
    for (int o = 16; o; o >>= 1) {
        s  += __shfl_xor_sync(0xffffffffu, s,  o);
        s2 += __shfl_xor_sync(0xffffffffu, s2, o);
    }
    __shared__ float shs[8], shs2[8];
    if (lane == 0) { shs[w] = s; shs2[w] = s2; }
    __syncthreads();
    if (w == 0) {
        float a  = (lane < 8) ? shs[lane]  : 0.f;
        float a2 = (lane < 8) ? shs2[lane] : 0.f;
        #pragma unroll
        for (int o = 4; o; o >>= 1) {
            a  += __shfl_xor_sync(0xffffffffu, a,  o);
            a2 += __shfl_xor_sync(0xffffffffu, a2, o);
        }
        if (lane == 0) { shs[0] = a; shs2[0] = a2; }
    }
    __syncthreads();
    float mu  = shs[0] * (1.f / DIMC);
    float var = shs2[0] * (1.f / DIMC) - mu * mu;
    float r = rsqrtf(var + 1e-5f);

    float* o = g_xn + (size_t)row * DIMC;
    o[t]       = (v0 - mu) * r * gamma[t]       + beta[t];
    o[t + 256] = (v1 - mu) * r * gamma[t + 256] + beta[t + 256];
    o[t + 512] = (v2 - mu) * r * gamma[t + 512] + beta[t + 512];
}

// ---------------- depthwise 5x5 conv (channels-last) ----------------
__global__ void dw_kernel(const float* __restrict__ w) {   // w: (768,1,5,5)
    int bpos = blockIdx.x;                 // b*1024 + tok
    int b = bpos >> 10, pos = bpos & 1023;
    int y = pos >> 5, x = pos & 31;
    const float* xn_b = g_xn + ((size_t)b * NTOK + 1) * DIMC;  // spatial tokens

    for (int c = threadIdx.x; c < DIMC; c += 256) {
        float acc = 0.f;
        const float* wc = w + c * 25;
        #pragma unroll
        for (int ky = 0; ky < 5; ky++) {
            int iy = y + ky - 2;
            if (iy < 0 || iy >= FHW) continue;
            #pragma unroll
            for (int kx = 0; kx < 5; kx++) {
                int ix = x + kx - 2;
                if (ix < 0 || ix >= FHW) continue;
                acc += wc[ky * 5 + kx] * xn_b[(size_t)(iy * 32 + ix) * DIMC + c];
            }
        }
        g_dw[(size_t)bpos * DIMC + c] = acc;
    }
}

// ---------------- tiled SGEMM: C[M,N] = A[M,K] @ B  (+bias) ----------------
// TB=false: B is K x N row-major.  TB=true: B is N x K row-major (C = A B^T).
template<bool TB, bool HAS_BIAS>
__global__ void sgemm_kernel(const float* __restrict__ A, const float* __restrict__ B,
                             const float* __restrict__ bias, float* __restrict__ C,
                             int M, int N, int K) {
    __shared__ float As[16][66];
    __shared__ float Bs[16][64];
    int bm = blockIdx.y * 64, bn = blockIdx.x * 64;
    int tid = threadIdx.x;                 // 256
    int tx = tid & 15, ty = tid >> 4;

    float acc[4][4];
    #pragma unroll
    for (int i = 0; i < 4; i++)
        #pragma unroll
        for (int j = 0; j < 4; j++) acc[i][j] = 0.f;

    for (int k0 = 0; k0 < K; k0 += 16) {
        // load A tile 64x16 (transposed into As[k][m])
        {
            int m = tid >> 2, kk = (tid & 3) * 4;
            float4 a = make_float4(0.f, 0.f, 0.f, 0.f);
            if (bm + m < M)
                a = *(const float4*)(A + (size_t)(bm + m) * K + k0 + kk);
            As[kk + 0][m] = a.x; As[kk + 1][m] = a.y;
            As[kk + 2][m] = a.z; As[kk + 3][m] = a.w;
        }
        // load B tile -> Bs[k][n]   (N always multiple of 64, K multiple of 16)
        if (!TB) {
            int kk = tid >> 4, nn = (tid & 15) * 4;
            float4 bv = *(const float4*)(B + (size_t)(k0 + kk) * N + bn + nn);
            *(float4*)&Bs[kk][nn] = bv;
        } else {
            int n = tid & 63, kk = (tid >> 6) * 4;
            float4 bv = *(const float4*)(B + (size_t)(bn + n) * K + k0 + kk);
            Bs[kk + 0][n] = bv.x; Bs[kk + 1][n] = bv.y;
            Bs[kk + 2][n] = bv.z; Bs[kk + 3][n] = bv.w;
        }
        __syncthreads();

        #pragma unroll
        for (int kk = 0; kk < 16; kk++) {
            float ar[4], br[4];
            #pragma unroll
            for (int i = 0; i < 4; i++) ar[i] = As[kk][ty * 4 + i];
            float4 b4 = *(const float4*)&Bs[kk][tx * 4];
            br[0] = b4.x; br[1] = b4.y; br[2] = b4.z; br[3] = b4.w;
            #pragma unroll
            for (int i = 0; i < 4; i++)
                #pragma unroll
                for (int j = 0; j < 4; j++)
                    acc[i][j] = fmaf(ar[i], br[j], acc[i][j]);
        }
        __syncthreads();
    }

    #pragma unroll
    for (int i = 0; i < 4; i++) {
        int m = bm + ty * 4 + i;
        if (m >= M) continue;
        float* cr = C + (size_t)m * N + bn + tx * 4;
        #pragma unroll
        for (int j = 0; j < 4; j++) {
            float v = acc[i][j];
            if (HAS_BIAS) v += bias[bn + tx * 4 + j];
            cr[j] = v;
        }
    }
}

// ---------------- q assembly + rope + kv split ----------------
__global__ void assemble_kernel(const float* __restrict__ sinp,
                                const float* __restrict__ cosp) {
    int row = blockIdx.x;                  // b*1025 + n
    int b = row / NTOK, n = row % NTOK;
    const float* pwrow = (n > 0) ? (g_pw + ((size_t)b * SP + (n - 1)) * DIMC) : nullptr;
    const float* kvrow = g_kv + (size_t)row * NKV;
    const float* xnrow = g_xn + (size_t)row * DIMC;
    int pos = n - 1;

    for (int c = threadIdx.x; c < DIMC; c += 256) {
        float qv, kv_;
        float vv = kvrow[DIMC + c];
        kv_ = kvrow[c];
        if (n == 0) {
            qv = xnrow[c];
        } else {
            qv = pwrow[c];
            int d = c & 63;
            if (d < NROT) {
                float cs = cosp[pos * NROT + d];
                float sn = sinp[pos * NROT + d];
                float qpart = pwrow[c ^ 1];
                float kpart = kvrow[c ^ 1];
                float qrot = (d & 1) ? qpart : -qpart;
                float krot = (d & 1) ? kpart : -kpart;
                qv  = qv  * cs + qrot * sn;
                kv_ = kv_ * cs + krot * sn;
            }
        }
        g_q[(size_t)row * DIMC + c] = qv;
        g_k[(size_t)row * DIMC + c] = kv_;
        g_v[(size_t)row * DIMC + c] = vv;
    }
}

// ---------------- flash attention (1 query / thread) ----------------
__global__ void __launch_bounds__(64)
attn_kernel() {
    int bh = blockIdx.x;                 // 0..95
    int b = bh / HEADS, h = bh % HEADS;
    int qi = blockIdx.y * 64 + threadIdx.x;
    bool valid = qi < NTOK;
    int qr = valid ? qi : 0;

    const float* qbase = g_q + ((size_t)b * NTOK) * DIMC + h * DH;
    const float* kbase = g_k + ((size_t)b * NTOK) * DIMC + h * DH;
    const float* vbase = g_v + ((size_t)b * NTOK) * DIMC + h * DH;

    float q[DH];
    #pragma unroll
    for (int d4 = 0; d4 < 16; d4++) {
        float4 t = *(const float4*)(qbase + (size_t)qr * DIMC + d4 * 4);
        q[d4*4+0] = t.x * 0.125f; q[d4*4+1] = t.y * 0.125f;
        q[d4*4+2] = t.z * 0.125f; q[d4*4+3] = t.w * 0.125f;
    }
    float o[DH];
    #pragma unroll
    for (int d = 0; d < DH; d++) o[d] = 0.f;
    float m = -1e30f, l = 0.f;

    __shared__ __align__(16) float ks[32][64];
    __shared__ __align__(16) float vs[32][64];

    for (int kt = 0; kt < NTOK; kt += 32) {
        __syncthreads();
        // cooperative tile load: 32 keys x 16 float4, per K and V
        for (int idx = threadIdx.x; idx < 512; idx += 64) {
            int j = idx >> 4, d4 = idx & 15;
            int key = kt + j;
            float4 kk = make_float4(0.f, 0.f, 0.f, 0.f);
            float4 vv = make_float4(0.f, 0.f, 0.f, 0.f);
            if (key < NTOK) {
                kk = *(const float4*)(kbase + (size_t)key * DIMC + d4 * 4);
                vv = *(const float4*)(vbase + (size_t)key * DIMC + d4 * 4);
            }
            *(float4*)&ks[j][d4 * 4] = kk;
            *(float4*)&vs[j][d4 * 4] = vv;
        }
        __syncthreads();

        float s[32];
        #pragma unroll
        for (int j = 0; j < 32; j++) {
            float a0 = 0.f, a1 = 0.f, a2 = 0.f, a3 = 0.f;
            #pragma unroll
            for (int d4 = 0; d4 < 16; d4++) {
                float4 kk = *(const float4*)&ks[j][d4 * 4];
                a0 = fmaf(q[d4*4+0], kk.x, a0);
                a1 = fmaf(q[d4*4+1], kk.y, a1);
                a2 = fmaf(q[d4*4+2], kk.z, a2);
                a3 = fmaf(q[d4*4+3], kk.w, a3);
            }
            s[j] = (a0 + a1) + (a2 + a3);
        }
        int nk = NTOK - kt;           // valid keys in this tile (uniform)
        #pragma unroll
        for (int j = 0; j < 32; j++)
            if (j >= nk) s[j] = -1e30f;

        float mt = m;
        #pragma unroll
        for (int j = 0; j < 32; j++) mt = fmaxf(mt, s[j]);
        float corr = __expf(m - mt);
        m = mt;
        l *= corr;
        #pragma unroll
        for (int d = 0; d < DH; d++) o[d] *= corr;

        #pragma unroll
        for (int j = 0; j < 32; j++) {
            float p = __expf(s[j] - mt);
            l += p;
            #pragma unroll
            for (int d4 = 0; d4 < 16; d4++) {
                float4 vv = *(const float4*)&vs[j][d4 * 4];
                o[d4*4+0] = fmaf(p, vv.x, o[d4*4+0]);
                o[d4*4+1] = fmaf(p, vv.y, o[d4*4+1]);
                o[d4*4+2] = fmaf(p, vv.z, o[d4*4+2]);
                o[d4*4+3] = fmaf(p, vv.w, o[d4*4+3]);
            }
        }
    }

    if (valid) {
        float inv = 1.f / l;
        float* op = g_ao + ((size_t)b * NTOK + qi) * DIMC + h * DH;
        #pragma unroll
        for (int d4 = 0; d4 < 16; d4++) {
            float4 t;
            t.x = o[d4*4+0] * inv; t.y = o[d4*4+1] * inv;
            t.z = o[d4*4+2] * inv; t.w = o[d4*4+3] * inv;
            *(float4*)(op + d4 * 4) = t;
        }
    }
}

// ---------------- launch ----------------
extern "C" void kernel_launch(void* const* d_in, const int* in_sizes, int n_in,
                              void* d_out, int out_size) {
    const float* x     = (const float*)d_in[0];
    const float* sinp  = (const float*)d_in[1];
    const float* cosp  = (const float*)d_in[2];
    const float* ln_g  = (const float*)d_in[3];
    const float* ln_b  = (const float*)d_in[4];
    const float* dw_w  = (const float*)d_in[5];
    const float* pw_w  = (const float*)d_in[6];
    const float* kv_w  = (const float*)d_in[7];
    const float* out_w = (const float*)d_in[8];
    const float* out_b = (const float*)d_in[9];
    float* out = (float*)d_out;

    float *p_xn, *p_dw, *p_pw, *p_kv, *p_ao;
    cudaGetSymbolAddress((void**)&p_xn, g_xn);
    cudaGetSymbolAddress((void**)&p_dw, g_dw);
    cudaGetSymbolAddress((void**)&p_pw, g_pw);
    cudaGetSymbolAddress((void**)&p_kv, g_kv);
    cudaGetSymbolAddress((void**)&p_ao, g_ao);

    // 1) layernorm
    ln_kernel<<<BB * NTOK, 256>>>(x, ln_g, ln_b);
    // 2) depthwise 5x5
    dw_kernel<<<BB * SP, 256>>>(dw_w);
    // 3) pointwise conv: g_pw = g_dw @ pw_w^T   (M=8192, N=768, K=768)
    sgemm_kernel<true, false><<<dim3(DIMC / 64, (BB * SP) / 64), 256>>>(
        p_dw, pw_w, nullptr, p_pw, BB * SP, DIMC, DIMC);
    // 4) kv gemm: g_kv = g_xn @ kv_w            (M=8200, N=1536, K=768)
    sgemm_kernel<false, false><<<dim3(NKV / 64, (BB * NTOK + 63) / 64), 256>>>(
        p_xn, kv_w, nullptr, p_kv, BB * NTOK, NKV, DIMC);
    // 5) q assembly + rope + kv split
    assemble_kernel<<<BB * NTOK, 256>>>(sinp, cosp);
    // 6) attention
    attn_kernel<<<dim3(BB * HEADS, (NTOK + 63) / 64), 64>>>();
    // 7) output projection + bias              (M=8200, N=768, K=768)
    sgemm_kernel<false, true><<<dim3(DIMC / 64, (BB * NTOK + 63) / 64), 256>>>(
        p_ao, out_w, out_b, out, BB * NTOK, DIMC, DIMC);
}

// round 2
// speedup vs baseline: 1.0172x; 1.0172x over previous
#include <cuda_runtime.h>
#include <math.h>

// ---------------- problem constants ----------------
#define BB    8
#define NTOK  1025
#define SP    1024      // spatial tokens (32x32)
#define FHW   32
#define DIMC  768
#define NKV   1536
#define HEADS 12
#define DH    64
#define NROT  32

// ---------------- scratch (static device arrays; allocation-free) ----------
__device__ float g_xn[BB*NTOK*DIMC];   // layernormed x
__device__ float g_dw[BB*SP*DIMC];     // depthwise conv out (b, tok, c)
__device__ float g_pw[BB*SP*DIMC];     // pointwise conv out (b, tok, c)
__device__ float g_kv[BB*NTOK*NKV];    // kv gemm out
__device__ float g_q [BB*NTOK*DIMC];   // q after rope (b, n, h*64+d)
__device__ float g_k [BB*NTOK*DIMC];
__device__ float g_v [BB*NTOK*DIMC];
__device__ float g_ao[BB*NTOK*DIMC];   // attention output

// ---------------- layernorm ----------------
__global__ void ln_kernel(const float* __restrict__ x,
                          const float* __restrict__ gamma,
                          const float* __restrict__ beta) {
    int row = blockIdx.x;               // 0..8199
    int t = threadIdx.x;                // 256 threads
    const float* xr = x + (size_t)row * DIMC;

    float v0 = xr[t], v1 = xr[t + 256], v2 = xr[t + 512];
    float s  = v0 + v1 + v2;
    float s2 = v0*v0 + v1*v1 + v2*v2;

    int lane = t & 31, w = t >> 5;
    #pragma unroll
    for (int o = 16; o; o >>= 1) {
        s  += __shfl_xor_sync(0xffffffffu, s,  o);
        s2 += __shfl_xor_sync(0xffffffffu, s2, o);
    }
    __shared__ float shs[8], shs2[8];
    if (lane == 0) { shs[w] = s; shs2[w] = s2; }
    __syncthreads();
    if (w == 0) {
        float a  = (lane < 8) ? shs[lane]  : 0.f;
        float a2 = (lane < 8) ? shs2[lane] : 0.f;
        #pragma unroll
        for (int o = 4; o; o >>= 1) {
            a  += __shfl_xor_sync(0xffffffffu, a,  o);
            a2 += __shfl_xor_sync(0xffffffffu, a2, o);
        }
        if (lane == 0) { shs[0] = a; shs2[0] = a2; }
    }
    __syncthreads();
    float mu  = shs[0] * (1.f / DIMC);
    float var = shs2[0] * (1.f / DIMC) - mu * mu;
    float r = rsqrtf(var + 1e-5f);

    float* o = g_xn + (size_t)row * DIMC;
    o[t]       = (v0 - mu) * r * gamma[t]       + beta[t];
    o[t + 256] = (v1 - mu) * r * gamma[t + 256] + beta[t + 256];
    o[t + 512] = (v2 - mu) * r * gamma[t + 512] + beta[t + 512];
}

// ---------------- depthwise 5x5 conv (channels-last) ----------------
__global__ void dw_kernel(const float* __restrict__ w) {   // w: (768,1,5,5)
    int bpos = blockIdx.x;                 // b*1024 + tok
    int b = bpos >> 10, pos = bpos & 1023;
    int y = pos >> 5, x = pos & 31;
    const float* xn_b = g_xn + ((size_t)b * NTOK + 1) * DIMC;  // spatial tokens

    for (int c = threadIdx.x; c < DIMC; c += 256) {
        float acc = 0.f;
        const float* wc = w + c * 25;
        #pragma unroll
        for (int ky = 0; ky < 5; ky++) {
            int iy = y + ky - 2;
            if (iy < 0 || iy >= FHW) continue;
            #pragma unroll
            for (int kx = 0; kx < 5; kx++) {
                int ix = x + kx - 2;
                if (ix < 0 || ix >= FHW) continue;
                acc += wc[ky * 5 + kx] * xn_b[(size_t)(iy * 32 + ix) * DIMC + c];
            }
        }
        g_dw[(size_t)bpos * DIMC + c] = acc;
    }
}

// ---------------- tiled SGEMM: 128x128x8, 8x8 microtile, double-buffered ----
// TB=false: B is K x N row-major.  TB=true: B is N x K row-major (C = A B^T).
// Requires: N % 128 == 0, K % 8 == 0 (both hold for all three GEMMs).
template<bool TB, bool HAS_BIAS>
__global__ void __launch_bounds__(256)
sgemm128(const float* __restrict__ A, const float* __restrict__ B,
         const float* __restrict__ bias, float* __restrict__ C,
         int M, int N, int K) {
    __shared__ float As[2][8][128];
    __shared__ float Bs[2][8][128];
    int bm = blockIdx.y * 128, bn = blockIdx.x * 128;
    int tid = threadIdx.x;
    int tx = tid & 15, ty = tid >> 4;

    // global-load mapping
    int arow = tid >> 1, akk = (tid & 1) * 4;      // A: 128 rows x 8k (and TB B)
    int bkrow = tid >> 5, bncol = (tid & 31) * 4;  // B NN: 8k x 128n

    const float4 zero4 = make_float4(0.f, 0.f, 0.f, 0.f);
    float4 fa, fb;

    // ---- prologue: load tile 0 ----
    fa = (bm + arow < M) ? *(const float4*)(A + (size_t)(bm + arow) * K + akk) : zero4;
    if (!TB) fb = *(const float4*)(B + (size_t)bkrow * N + bn + bncol);
    else     fb = *(const float4*)(B + (size_t)(bn + arow) * K + akk);

    As[0][akk + 0][arow] = fa.x; As[0][akk + 1][arow] = fa.y;
    As[0][akk + 2][arow] = fa.z; As[0][akk + 3][arow] = fa.w;
    if (!TB) {
        *(float4*)&Bs[0][bkrow][bncol] = fb;
    } else {
        Bs[0][akk + 0][arow] = fb.x; Bs[0][akk + 1][arow] = fb.y;
        Bs[0][akk + 2][arow] = fb.z; Bs[0][akk + 3][arow] = fb.w;
    }
    __syncthreads();

    float acc[8][8];
    #pragma unroll
    for (int i = 0; i < 8; i++)
        #pragma unroll
        for (int j = 0; j < 8; j++) acc[i][j] = 0.f;

    int NT = K >> 3;
    for (int t = 0; t < NT; t++) {
        int cur = t & 1;
        if (t + 1 < NT) {
            int k0 = (t + 1) * 8;
            fa = (bm + arow < M) ? *(const float4*)(A + (size_t)(bm + arow) * K + k0 + akk) : zero4;
            if (!TB) fb = *(const float4*)(B + (size_t)(k0 + bkrow) * N + bn + bncol);
            else     fb = *(const float4*)(B + (size_t)(bn + arow) * K + k0 + akk);
        }
        #pragma unroll
        for (int kk = 0; kk < 8; kk++) {
            float4 a0 = *(const float4*)&As[cur][kk][ty * 4];
            float4 a1 = *(const float4*)&As[cur][kk][ty * 4 + 64];
            float4 b0 = *(const float4*)&Bs[cur][kk][tx * 4];
            float4 b1 = *(const float4*)&Bs[cur][kk][tx * 4 + 64];
            float ar[8] = {a0.x, a0.y, a0.z, a0.w, a1.x, a1.y, a1.z, a1.w};
            float br[8] = {b0.x, b0.y, b0.z, b0.w, b1.x, b1.y, b1.z, b1.w};
            #pragma unroll
            for (int i = 0; i < 8; i++)
                #pragma unroll
                for (int j = 0; j < 8; j++)
                    acc[i][j] = fmaf(ar[i], br[j], acc[i][j]);
        }
        if (t + 1 < NT) {
            int nxt = cur ^ 1;
            As[nxt][akk + 0][arow] = fa.x; As[nxt][akk + 1][arow] = fa.y;
            As[nxt][akk + 2][arow] = fa.z; As[nxt][akk + 3][arow] = fa.w;
            if (!TB) {
                *(float4*)&Bs[nxt][bkrow][bncol] = fb;
            } else {
                Bs[nxt][akk + 0][arow] = fb.x; Bs[nxt][akk + 1][arow] = fb.y;
                Bs[nxt][akk + 2][arow] = fb.z; Bs[nxt][akk + 3][arow] = fb.w;
            }
            __syncthreads();
        }
    }

    // ---- epilogue ----
    #pragma unroll
    for (int i = 0; i < 8; i++) {
        int row = bm + ty * 4 + (i & 3) + (i >> 2) * 64;
        if (row >= M) continue;
        float* cr = C + (size_t)row * N + bn;
        float4 c0, c1;
        c0.x = acc[i][0]; c0.y = acc[i][1]; c0.z = acc[i][2]; c0.w = acc[i][3];
        c1.x = acc[i][4]; c1.y = acc[i][5]; c1.z = acc[i][6]; c1.w = acc[i][7];
        if (HAS_BIAS) {
            const float4 g0 = *(const float4*)(bias + bn + tx * 4);
            const float4 g1 = *(const float4*)(bias + bn + tx * 4 + 64);
            c0.x += g0.x; c0.y += g0.y; c0.z += g0.z; c0.w += g0.w;
            c1.x += g1.x; c1.y += g1.y; c1.z += g1.z; c1.w += g1.w;
        }
        *(float4*)(cr + tx * 4)      = c0;
        *(float4*)(cr + tx * 4 + 64) = c1;
    }
}

// ---------------- q assembly + rope + kv split ----------------
__global__ void assemble_kernel(const float* __restrict__ sinp,
                                const float* __restrict__ cosp) {
    int row = blockIdx.x;                  // b*1025 + n
    int b = row / NTOK, n = row % NTOK;
    const float* pwrow = (n > 0) ? (g_pw + ((size_t)b * SP + (n - 1)) * DIMC) : nullptr;
    const float* kvrow = g_kv + (size_t)row * NKV;
    const float* xnrow = g_xn + (size_t)row * DIMC;
    int pos = n - 1;

    for (int c = threadIdx.x; c < DIMC; c += 256) {
        float qv, kv_;
        float vv = kvrow[DIMC + c];
        kv_ = kvrow[c];
        if (n == 0) {
            qv = xnrow[c];
        } else {
            qv = pwrow[c];
            int d = c & 63;
            if (d < NROT) {
                float cs = cosp[pos * NROT + d];
                float sn = sinp[pos * NROT + d];
                float qpart = pwrow[c ^ 1];
                float kpart = kvrow[c ^ 1];
                float qrot = (d & 1) ? qpart : -qpart;
                float krot = (d & 1) ? kpart : -kpart;
                qv  = qv  * cs + qrot * sn;
                kv_ = kv_ * cs + krot * sn;
            }
        }
        g_q[(size_t)row * DIMC + c] = qv;
        g_k[(size_t)row * DIMC + c] = kv_;
        g_v[(size_t)row * DIMC + c] = vv;
    }
}

// ---------------- flash attention (1 query / thread, 16-key score chunks) ---
__global__ void __launch_bounds__(64)
attn_kernel() {
    int bh = blockIdx.x;                 // 0..95
    int b = bh / HEADS, h = bh % HEADS;
    int qi = blockIdx.y * 64 + threadIdx.x;
    bool valid = qi < NTOK;
    int qr = valid ? qi : 0;

    const float* qbase = g_q + ((size_t)b * NTOK) * DIMC + h * DH;
    const float* kbase = g_k + ((size_t)b * NTOK) * DIMC + h * DH;
    const float* vbase = g_v + ((size_t)b * NTOK) * DIMC + h * DH;

    float q[DH];
    #pragma unroll
    for (int d4 = 0; d4 < 16; d4++) {
        float4 t = *(const float4*)(qbase + (size_t)qr * DIMC + d4 * 4);
        q[d4*4+0] = t.x * 0.125f; q[d4*4+1] = t.y * 0.125f;
        q[d4*4+2] = t.z * 0.125f; q[d4*4+3] = t.w * 0.125f;
    }
    float o[DH];
    #pragma unroll
    for (int d = 0; d < DH; d++) o[d] = 0.f;
    float m = -1e30f, l = 0.f;

    __shared__ __align__(16) float ks[32][64];
    __shared__ __align__(16) float vs[32][64];

    for (int kt = 0; kt < NTOK; kt += 32) {
        __syncthreads();
        for (int idx = threadIdx.x; idx < 512; idx += 64) {
            int j = idx >> 4, d4 = idx & 15;
            int key = kt + j;
            float4 kk = make_float4(0.f, 0.f, 0.f, 0.f);
            float4 vv = make_float4(0.f, 0.f, 0.f, 0.f);
            if (key < NTOK) {
                kk = *(const float4*)(kbase + (size_t)key * DIMC + d4 * 4);
                vv = *(const float4*)(vbase + (size_t)key * DIMC + d4 * 4);
            }
            *(float4*)&ks[j][d4 * 4] = kk;
            *(float4*)&vs[j][d4 * 4] = vv;
        }
        __syncthreads();

        #pragma unroll
        for (int c = 0; c < 2; c++) {
            int base = c * 16;
            float s[16];
            #pragma unroll
            for (int j = 0; j < 16; j++) {
                float a0 = 0.f, a1 = 0.f, a2 = 0.f, a3 = 0.f;
                #pragma unroll
                for (int d4 = 0; d4 < 16; d4++) {
                    float4 kk = *(const float4*)&ks[base + j][d4 * 4];
                    a0 = fmaf(q[d4*4+0], kk.x, a0);
                    a1 = fmaf(q[d4*4+1], kk.y, a1);
                    a2 = fmaf(q[d4*4+2], kk.z, a2);
                    a3 = fmaf(q[d4*4+3], kk.w, a3);
                }
                s[j] = (a0 + a1) + (a2 + a3);
            }
            int nk = NTOK - kt - base;        // valid keys in this chunk
            #pragma unroll
            for (int j = 0; j < 16; j++)
                if (j >= nk) s[j] = -1e30f;

            float mt = m;
            #pragma unroll
            for (int j = 0; j < 16; j++) mt = fmaxf(mt, s[j]);
            float corr = __expf(m - mt);
            m = mt;
            l *= corr;
            #pragma unroll
            for (int d = 0; d < DH; d++) o[d] *= corr;

            #pragma unroll
            for (int j = 0; j < 16; j++) {
                float p = __expf(s[j] - mt);
                l += p;
                #pragma unroll
                for (int d4 = 0; d4 < 16; d4++) {
                    float4 vv = *(const float4*)&vs[base + j][d4 * 4];
                    o[d4*4+0] = fmaf(p, vv.x, o[d4*4+0]);
                    o[d4*4+1] = fmaf(p, vv.y, o[d4*4+1]);
                    o[d4*4+2] = fmaf(p, vv.z, o[d4*4+2]);
                    o[d4*4+3] = fmaf(p, vv.w, o[d4*4+3]);
                }
            }
        }
    }

    if (valid) {
        float inv = 1.f / l;
        float* op = g_ao + ((size_t)b * NTOK + qi) * DIMC + h * DH;
        #pragma unroll
        for (int d4 = 0; d4 < 16; d4++) {
            float4 t;
            t.x = o[d4*4+0] * inv; t.y = o[d4*4+1] * inv;
            t.z = o[d4*4+2] * inv; t.w = o[d4*4+3] * inv;
            *(float4*)(op + d4 * 4) = t;
        }
    }
}

// ---------------- launch ----------------
extern "C" void kernel_launch(void* const* d_in, const int* in_sizes, int n_in,
                              void* d_out, int out_size) {
    const float* x     = (const float*)d_in[0];
    const float* sinp  = (const float*)d_in[1];
    const float* cosp  = (const float*)d_in[2];
    const float* ln_g  = (const float*)d_in[3];
    const float* ln_b  = (const float*)d_in[4];
    const float* dw_w  = (const float*)d_in[5];
    const float* pw_w  = (const float*)d_in[6];
    const float* kv_w  = (const float*)d_in[7];
    const float* out_w = (const float*)d_in[8];
    const float* out_b = (const float*)d_in[9];
    float* out = (float*)d_out;

    float *p_xn, *p_dw, *p_pw, *p_kv, *p_ao;
    cudaGetSymbolAddress((void**)&p_xn, g_xn);
    cudaGetSymbolAddress((void**)&p_dw, g_dw);
    cudaGetSymbolAddress((void**)&p_pw, g_pw);
    cudaGetSymbolAddress((void**)&p_kv, g_kv);
    cudaGetSymbolAddress((void**)&p_ao, g_ao);

    // 1) layernorm
    ln_kernel<<<BB * NTOK, 256>>>(x, ln_g, ln_b);
    // 2) depthwise 5x5
    dw_kernel<<<BB * SP, 256>>>(dw_w);
    // 3) pointwise conv: g_pw = g_dw @ pw_w^T   (M=8192, N=768, K=768)
    sgemm128<true, false><<<dim3(DIMC / 128, (BB * SP) / 128), 256>>>(
        p_dw, pw_w, nullptr, p_pw, BB * SP, DIMC, DIMC);
    // 4) kv gemm: g_kv = g_xn @ kv_w            (M=8200, N=1536, K=768)
    sgemm128<false, false><<<dim3(NKV / 128, (BB * NTOK + 127) / 128), 256>>>(
        p_xn, kv_w, nullptr, p_kv, BB * NTOK, NKV, DIMC);
    // 5) q assembly + rope + kv split
    assemble_kernel<<<BB * NTOK, 256>>>(sinp, cosp);
    // 6) attention
    attn_kernel<<<dim3(BB * HEADS, (NTOK + 63) / 64), 64>>>();
    // 7) output projection + bias              (M=8200, N=768, K=768)
    sgemm128<false, true><<<dim3(DIMC / 128, (BB * NTOK + 127) / 128), 256>>>(
        p_ao, out_w, out_b, out, BB * NTOK, DIMC, DIMC);
}

// round 3
// speedup vs baseline: 1.3314x; 1.3089x over previous
#include <cuda_runtime.h>
#include <math.h>

// ---------------- problem constants ----------------
#define BB    8
#define NTOK  1025
#define SP    1024
#define FHW   32
#define DIMC  768
#define NKV   1536
#define HEADS 12
#define DH    64
#define NROT  32

// ---------------- scratch ----------------
__device__ float g_xn[BB*NTOK*DIMC];
__device__ float g_dw[BB*SP*DIMC];
__device__ float g_pw[BB*SP*DIMC];
__device__ float g_kv[BB*NTOK*NKV];
__device__ float g_q [BB*NTOK*DIMC];
__device__ float g_k [BB*NTOK*DIMC];
__device__ float g_v [BB*NTOK*DIMC];
__device__ float g_ao[BB*NTOK*DIMC];

// ---------------- layernorm ----------------
__global__ void ln_kernel(const float* __restrict__ x,
                          const float* __restrict__ gamma,
                          const float* __restrict__ beta) {
    int row = blockIdx.x;
    int t = threadIdx.x;
    const float* xr = x + (size_t)row * DIMC;

    float v0 = xr[t], v1 = xr[t + 256], v2 = xr[t + 512];
    float s  = v0 + v1 + v2;
    float s2 = v0*v0 + v1*v1 + v2*v2;

    int lane = t & 31, w = t >> 5;
    #pragma unroll
    for (int o = 16; o; o >>= 1) {
        s  += __shfl_xor_sync(0xffffffffu, s,  o);
        s2 += __shfl_xor_sync(0xffffffffu, s2, o);
    }
    __shared__ float shs[8], shs2[8];
    if (lane == 0) { shs[w] = s; shs2[w] = s2; }
    __syncthreads();
    if (w == 0) {
        float a  = (lane < 8) ? shs[lane]  : 0.f;
        float a2 = (lane < 8) ? shs2[lane] : 0.f;
        #pragma unroll
        for (int o = 4; o; o >>= 1) {
            a  += __shfl_xor_sync(0xffffffffu, a,  o);
            a2 += __shfl_xor_sync(0xffffffffu, a2, o);
        }
        if (lane == 0) { shs[0] = a; shs2[0] = a2; }
    }
    __syncthreads();
    float mu  = shs[0] * (1.f / DIMC);
    float var = shs2[0] * (1.f / DIMC) - mu * mu;
    float r = rsqrtf(var + 1e-5f);

    float* o = g_xn + (size_t)row * DIMC;
    o[t]       = (v0 - mu) * r * gamma[t]       + beta[t];
    o[t + 256] = (v1 - mu) * r * gamma[t + 256] + beta[t + 256];
    o[t + 512] = (v2 - mu) * r * gamma[t + 512] + beta[t + 512];
}

// ---------------- depthwise 5x5 conv ----------------
__global__ void dw_kernel(const float* __restrict__ w) {
    int bpos = blockIdx.x;
    int b = bpos >> 10, pos = bpos & 1023;
    int y = pos >> 5, x = pos & 31;
    const float* xn_b = g_xn + ((size_t)b * NTOK + 1) * DIMC;

    for (int c = threadIdx.x; c < DIMC; c += 256) {
        float acc = 0.f;
        const float* wc = w + c * 25;
        #pragma unroll
        for (int ky = 0; ky < 5; ky++) {
            int iy = y + ky - 2;
            if (iy < 0 || iy >= FHW) continue;
            #pragma unroll
            for (int kx = 0; kx < 5; kx++) {
                int ix = x + kx - 2;
                if (ix < 0 || ix >= FHW) continue;
                acc += wc[ky * 5 + kx] * xn_b[(size_t)(iy * 32 + ix) * DIMC + c];
            }
        }
        g_dw[(size_t)bpos * DIMC + c] = acc;
    }
}

// ---------------- tf32 tensor-core GEMM ----------------
// C[M,N] = A[M,K] @ B (+bias). TB=false: B is KxN. TB=true: B is NxK (C=A B^T).
// Block 128x128x16, 8 warps (2m x 4n), warp 64x32, mma m16n8k8 tf32.
__device__ __forceinline__ unsigned f2tf(float f) {
    unsigned r;
    asm("cvt.rna.tf32.f32 %0, %1;" : "=r"(r) : "f"(f));
    return r;
}

__device__ __forceinline__ void mma8(float* c, const unsigned* a, const unsigned* b) {
    asm volatile(
        "mma.sync.aligned.m16n8k8.row.col.f32.tf32.tf32.f32 "
        "{%0,%1,%2,%3}, {%4,%5,%6,%7}, {%8,%9}, {%0,%1,%2,%3};"
        : "+f"(c[0]), "+f"(c[1]), "+f"(c[2]), "+f"(c[3])
        : "r"(a[0]), "r"(a[1]), "r"(a[2]), "r"(a[3]), "r"(b[0]), "r"(b[1]));
}

#define SMS 136   // smem row stride (banks: 8*t4+g -> conflict-free frag loads)

template<bool TB, bool HAS_BIAS>
__global__ void __launch_bounds__(256)
mma_gemm(const float* __restrict__ A, const float* __restrict__ B,
         const float* __restrict__ bias, float* __restrict__ C,
         int M, int N, int K) {
    __shared__ unsigned As[2][16][SMS];
    __shared__ unsigned Bs[2][16][SMS];
    int tid = threadIdx.x;
    int lane = tid & 31, warp = tid >> 5;
    int wm = warp >> 2, wn = warp & 3;
    int g = lane >> 2, t4 = lane & 3;
    int bm = blockIdx.y * 128, bn = blockIdx.x * 128;

    int ar = tid >> 1, ak = (tid & 1) * 8;     // A (and TB-B) staging: row, k-offset
    int bk = tid >> 4, bn8 = (tid & 15) * 8;   // NN-B staging

    float acc[4][4][4];
    #pragma unroll
    for (int i = 0; i < 4; i++)
        #pragma unroll
        for (int j = 0; j < 4; j++)
            #pragma unroll
            for (int r = 0; r < 4; r++) acc[i][j][r] = 0.f;

    unsigned ua[8], ub[8];

    // ---- global load of k-tile k0 into regs (tf32-converted) ----
    auto gload = [&](int k0) {
        float4 a0 = make_float4(0.f,0.f,0.f,0.f), a1 = a0;
        if (bm + ar < M) {
            const float* p = A + (size_t)(bm + ar) * K + k0 + ak;
            a0 = *(const float4*)p; a1 = *(const float4*)(p + 4);
        }
        ua[0]=f2tf(a0.x); ua[1]=f2tf(a0.y); ua[2]=f2tf(a0.z); ua[3]=f2tf(a0.w);
        ua[4]=f2tf(a1.x); ua[5]=f2tf(a1.y); ua[6]=f2tf(a1.z); ua[7]=f2tf(a1.w);
        if (!TB) {
            const float* p = B + (size_t)(k0 + bk) * N + bn + bn8;
            float4 b0 = *(const float4*)p, b1 = *(const float4*)(p + 4);
            ub[0]=f2tf(b0.x); ub[1]=f2tf(b0.y); ub[2]=f2tf(b0.z); ub[3]=f2tf(b0.w);
            ub[4]=f2tf(b1.x); ub[5]=f2tf(b1.y); ub[6]=f2tf(b1.z); ub[7]=f2tf(b1.w);
        } else {
            const float* p = B + (size_t)(bn + ar) * K + k0 + ak;
            float4 b0 = *(const float4*)p, b1 = *(const float4*)(p + 4);
            ub[0]=f2tf(b0.x); ub[1]=f2tf(b0.y); ub[2]=f2tf(b0.z); ub[3]=f2tf(b0.w);
            ub[4]=f2tf(b1.x); ub[5]=f2tf(b1.y); ub[6]=f2tf(b1.z); ub[7]=f2tf(b1.w);
        }
    };
    auto sstore = [&](int st) {
        #pragma unroll
        for (int i = 0; i < 8; i++) As[st][ak + i][ar] = ua[i];
        if (!TB) {
            *(uint4*)&Bs[st][bk][bn8]     = make_uint4(ub[0], ub[1], ub[2], ub[3]);
            *(uint4*)&Bs[st][bk][bn8 + 4] = make_uint4(ub[4], ub[5], ub[6], ub[7]);
        } else {
            #pragma unroll
            for (int i = 0; i < 8; i++) Bs[st][ak + i][ar] = ub[i];
        }
    };

    gload(0);
    sstore(0);
    __syncthreads();

    int NT = K >> 4;
    for (int t = 0; t < NT; t++) {
        int cur = t & 1;
        if (t + 1 < NT) gload((t + 1) * 16);

        #pragma unroll
        for (int kb = 0; kb < 16; kb += 8) {
            unsigned af[4][4], bf[4][2];
            #pragma unroll
            for (int mi = 0; mi < 4; mi++) {
                int m0 = wm * 64 + mi * 16 + g;
                af[mi][0] = As[cur][kb + t4][m0];
                af[mi][1] = As[cur][kb + t4][m0 + 8];
                af[mi][2] = As[cur][kb + t4 + 4][m0];
                af[mi][3] = As[cur][kb + t4 + 4][m0 + 8];
            }
            #pragma unroll
            for (int ni = 0; ni < 4; ni++) {
                int n0 = wn * 32 + ni * 8 + g;
                bf[ni][0] = Bs[cur][kb + t4][n0];
                bf[ni][1] = Bs[cur][kb + t4 + 4][n0];
            }
            #pragma unroll
            for (int mi = 0; mi < 4; mi++)
                #pragma unroll
                for (int ni = 0; ni < 4; ni++)
                    mma8(acc[mi][ni], af[mi], bf[ni]);
        }

        if (t + 1 < NT) {
            sstore(cur ^ 1);
            __syncthreads();
        }
    }

    // ---- epilogue ----
    #pragma unroll
    for (int mi = 0; mi < 4; mi++) {
        int row0 = bm + wm * 64 + mi * 16 + g;
        int row1 = row0 + 8;
        #pragma unroll
        for (int ni = 0; ni < 4; ni++) {
            int col = bn + wn * 32 + ni * 8 + 2 * t4;
            float b0 = 0.f, b1 = 0.f;
            if (HAS_BIAS) { b0 = bias[col]; b1 = bias[col + 1]; }
            if (row0 < M) {
                float2 v = make_float2(acc[mi][ni][0] + b0, acc[mi][ni][1] + b1);
                *(float2*)(C + (size_t)row0 * N + col) = v;
            }
            if (row1 < M) {
                float2 v = make_float2(acc[mi][ni][2] + b0, acc[mi][ni][3] + b1);
                *(float2*)(C + (size_t)row1 * N + col) = v;
            }
        }
    }
}

// ---------------- q assembly + rope + kv split ----------------
__global__ void assemble_kernel(const float* __restrict__ sinp,
                                const float* __restrict__ cosp) {
    int row = blockIdx.x;
    int b = row / NTOK, n = row % NTOK;
    const float* pwrow = (n > 0) ? (g_pw + ((size_t)b * SP + (n - 1)) * DIMC) : nullptr;
    const float* kvrow = g_kv + (size_t)row * NKV;
    const float* xnrow = g_xn + (size_t)row * DIMC;
    int pos = n - 1;

    for (int c = threadIdx.x; c < DIMC; c += 256) {
        float qv, kv_;
        float vv = kvrow[DIMC + c];
        kv_ = kvrow[c];
        if (n == 0) {
            qv = xnrow[c];
        } else {
            qv = pwrow[c];
            int d = c & 63;
            if (d < NROT) {
                float cs = cosp[pos * NROT + d];
                float sn = sinp[pos * NROT + d];
                float qpart = pwrow[c ^ 1];
                float kpart = kvrow[c ^ 1];
                float qrot = (d & 1) ? qpart : -qpart;
                float krot = (d & 1) ? kpart : -kpart;
                qv  = qv  * cs + qrot * sn;
                kv_ = kv_ * cs + krot * sn;
            }
        }
        g_q[(size_t)row * DIMC + c] = qv;
        g_k[(size_t)row * DIMC + c] = kv_;
        g_v[(size_t)row * DIMC + c] = vv;
    }
}

// ---------------- flash attention (1 query / thread, 128 thr/block) --------
__global__ void __launch_bounds__(128)
attn_kernel() {
    int bh = blockIdx.x;
    int b = bh / HEADS, h = bh % HEADS;
    int qi = blockIdx.y * 128 + threadIdx.x;
    bool valid = qi < NTOK;
    int qr = valid ? qi : 0;

    const float* qbase = g_q + ((size_t)b * NTOK) * DIMC + h * DH;
    const float* kbase = g_k + ((size_t)b * NTOK) * DIMC + h * DH;
    const float* vbase = g_v + ((size_t)b * NTOK) * DIMC + h * DH;

    float q[DH];
    #pragma unroll
    for (int d4 = 0; d4 < 16; d4++) {
        float4 t = *(const float4*)(qbase + (size_t)qr * DIMC + d4 * 4);
        q[d4*4+0] = t.x * 0.125f; q[d4*4+1] = t.y * 0.125f;
        q[d4*4+2] = t.z * 0.125f; q[d4*4+3] = t.w * 0.125f;
    }
    float o[DH];
    #pragma unroll
    for (int d = 0; d < DH; d++) o[d] = 0.f;
    float m = -1e30f, l = 0.f;

    __shared__ __align__(16) float ks[32][64];
    __shared__ __align__(16) float vs[32][64];

    for (int kt = 0; kt < NTOK; kt += 32) {
        __syncthreads();
        for (int idx = threadIdx.x; idx < 512; idx += 128) {
            int j = idx >> 4, d4 = idx & 15;
            int key = kt + j;
            float4 kk = make_float4(0.f, 0.f, 0.f, 0.f);
            float4 vv = make_float4(0.f, 0.f, 0.f, 0.f);
            if (key < NTOK) {
                kk = *(const float4*)(kbase + (size_t)key * DIMC + d4 * 4);
                vv = *(const float4*)(vbase + (size_t)key * DIMC + d4 * 4);
            }
            *(float4*)&ks[j][d4 * 4] = kk;
            *(float4*)&vs[j][d4 * 4] = vv;
        }
        __syncthreads();

        #pragma unroll
        for (int c = 0; c < 2; c++) {
            int base = c * 16;
            float s[16];
            #pragma unroll
            for (int j = 0; j < 16; j++) {
                float a0 = 0.f, a1 = 0.f, a2 = 0.f, a3 = 0.f;
                #pragma unroll
                for (int d4 = 0; d4 < 16; d4++) {
                    float4 kk = *(const float4*)&ks[base + j][d4 * 4];
                    a0 = fmaf(q[d4*4+0], kk.x, a0);
                    a1 = fmaf(q[d4*4+1], kk.y, a1);
                    a2 = fmaf(q[d4*4+2], kk.z, a2);
                    a3 = fmaf(q[d4*4+3], kk.w, a3);
                }
                s[j] = (a0 + a1) + (a2 + a3);
            }
            int nk = NTOK - kt - base;
            #pragma unroll
            for (int j = 0; j < 16; j++)
                if (j >= nk) s[j] = -1e30f;

            float mt = m;
            #pragma unroll
            for (int j = 0; j < 16; j++) mt = fmaxf(mt, s[j]);
            float corr = __expf(m - mt);
            m = mt;
            l *= corr;
            #pragma unroll
            for (int d = 0; d < DH; d++) o[d] *= corr;

            #pragma unroll
            for (int j = 0; j < 16; j++) {
                float p = __expf(s[j] - mt);
                l += p;
                #pragma unroll
                for (int d4 = 0; d4 < 16; d4++) {
                    float4 vv = *(const float4*)&vs[base + j][d4 * 4];
                    o[d4*4+0] = fmaf(p, vv.x, o[d4*4+0]);
                    o[d4*4+1] = fmaf(p, vv.y, o[d4*4+1]);
                    o[d4*4+2] = fmaf(p, vv.z, o[d4*4+2]);
                    o[d4*4+3] = fmaf(p, vv.w, o[d4*4+3]);
                }
            }
        }
    }

    if (valid) {
        float inv = 1.f / l;
        float* op = g_ao + ((size_t)b * NTOK + qi) * DIMC + h * DH;
        #pragma unroll
        for (int d4 = 0; d4 < 16; d4++) {
            float4 t;
            t.x = o[d4*4+0] * inv; t.y = o[d4*4+1] * inv;
            t.z = o[d4*4+2] * inv; t.w = o[d4*4+3] * inv;
            *(float4*)(op + d4 * 4) = t;
        }
    }
}

// ---------------- launch ----------------
extern "C" void kernel_launch(void* const* d_in, const int* in_sizes, int n_in,
                              void* d_out, int out_size) {
    const float* x     = (const float*)d_in[0];
    const float* sinp  = (const float*)d_in[1];
    const float* cosp  = (const float*)d_in[2];
    const float* ln_g  = (const float*)d_in[3];
    const float* ln_b  = (const float*)d_in[4];
    const float* dw_w  = (const float*)d_in[5];
    const float* pw_w  = (const float*)d_in[6];
    const float* kv_w  = (const float*)d_in[7];
    const float* out_w = (const float*)d_in[8];
    const float* out_b = (const float*)d_in[9];
    float* out = (float*)d_out;

    float *p_xn, *p_dw, *p_pw, *p_kv, *p_ao;
    cudaGetSymbolAddress((void**)&p_xn, g_xn);
    cudaGetSymbolAddress((void**)&p_dw, g_dw);
    cudaGetSymbolAddress((void**)&p_pw, g_pw);
    cudaGetSymbolAddress((void**)&p_kv, g_kv);
    cudaGetSymbolAddress((void**)&p_ao, g_ao);

    ln_kernel<<<BB * NTOK, 256>>>(x, ln_g, ln_b);
    dw_kernel<<<BB * SP, 256>>>(dw_w);
    // pointwise conv: g_pw = g_dw @ pw_w^T   (M=8192, N=768, K=768)
    mma_gemm<true, false><<<dim3(DIMC / 128, (BB * SP) / 128), 256>>>(
        p_dw, pw_w, nullptr, p_pw, BB * SP, DIMC, DIMC);
    // kv gemm: g_kv = g_xn @ kv_w            (M=8200, N=1536, K=768)
    mma_gemm<false, false><<<dim3(NKV / 128, (BB * NTOK + 127) / 128), 256>>>(
        p_xn, kv_w, nullptr, p_kv, BB * NTOK, NKV, DIMC);
    assemble_kernel<<<BB * NTOK, 256>>>(sinp, cosp);
    attn_kernel<<<dim3(BB * HEADS, (NTOK + 127) / 128), 128>>>();
    // output projection + bias              (M=8200, N=768, K=768)
    mma_gemm<false, true><<<dim3(DIMC / 128, (BB * NTOK + 127) / 128), 256>>>(
        p_ao, out_w, out_b, out, BB * NTOK, DIMC, DIMC);
}

// round 4
// speedup vs baseline: 2.6998x; 2.0278x over previous
#include <cuda_runtime.h>
#include <math.h>

// ---------------- problem constants ----------------
#define BB    8
#define NTOK  1025
#define SP    1024
#define FHW   32
#define DIMC  768
#define NKV   1536
#define HEADS 12
#define DH    64
#define NROT  32

// ---------------- scratch ----------------
__device__ float g_xn[BB*NTOK*DIMC];
__device__ float g_dw[BB*SP*DIMC];
__device__ float g_pw[BB*SP*DIMC];
__device__ float g_kv[BB*NTOK*NKV];
__device__ float g_q [BB*NTOK*DIMC];
__device__ float g_k [BB*NTOK*DIMC];
__device__ float g_v [BB*NTOK*DIMC];
__device__ float g_ao[BB*NTOK*DIMC];

// ---------------- tf32 helpers ----------------
__device__ __forceinline__ unsigned f2tf(float f) {
    unsigned r;
    asm("cvt.rna.tf32.f32 %0, %1;" : "=r"(r) : "f"(f));
    return r;
}
__device__ __forceinline__ void mma8(float* c, const unsigned* a, const unsigned* b) {
    asm volatile(
        "mma.sync.aligned.m16n8k8.row.col.f32.tf32.tf32.f32 "
        "{%0,%1,%2,%3}, {%4,%5,%6,%7}, {%8,%9}, {%0,%1,%2,%3};"
        : "+f"(c[0]), "+f"(c[1]), "+f"(c[2]), "+f"(c[3])
        : "r"(a[0]), "r"(a[1]), "r"(a[2]), "r"(a[3]), "r"(b[0]), "r"(b[1]));
}

// ---------------- layernorm ----------------
__global__ void ln_kernel(const float* __restrict__ x,
                          const float* __restrict__ gamma,
                          const float* __restrict__ beta) {
    int row = blockIdx.x;
    int t = threadIdx.x;
    const float* xr = x + (size_t)row * DIMC;

    float v0 = xr[t], v1 = xr[t + 256], v2 = xr[t + 512];
    float s  = v0 + v1 + v2;
    float s2 = v0*v0 + v1*v1 + v2*v2;

    int lane = t & 31, w = t >> 5;
    #pragma unroll
    for (int o = 16; o; o >>= 1) {
        s  += __shfl_xor_sync(0xffffffffu, s,  o);
        s2 += __shfl_xor_sync(0xffffffffu, s2, o);
    }
    __shared__ float shs[8], shs2[8];
    if (lane == 0) { shs[w] = s; shs2[w] = s2; }
    __syncthreads();
    if (w == 0) {
        float a  = (lane < 8) ? shs[lane]  : 0.f;
        float a2 = (lane < 8) ? shs2[lane] : 0.f;
        #pragma unroll
        for (int o = 4; o; o >>= 1) {
            a  += __shfl_xor_sync(0xffffffffu, a,  o);
            a2 += __shfl_xor_sync(0xffffffffu, a2, o);
        }
        if (lane == 0) { shs[0] = a; shs2[0] = a2; }
    }
    __syncthreads();
    float mu  = shs[0] * (1.f / DIMC);
    float var = shs2[0] * (1.f / DIMC) - mu * mu;
    float r = rsqrtf(var + 1e-5f);

    float* o = g_xn + (size_t)row * DIMC;
    o[t]       = (v0 - mu) * r * gamma[t]       + beta[t];
    o[t + 256] = (v1 - mu) * r * gamma[t + 256] + beta[t + 256];
    o[t + 512] = (v2 - mu) * r * gamma[t + 512] + beta[t + 512];
}

// ---------------- depthwise 5x5 conv ----------------
__global__ void dw_kernel(const float* __restrict__ w) {
    int bpos = blockIdx.x;
    int b = bpos >> 10, pos = bpos & 1023;
    int y = pos >> 5, x = pos & 31;
    const float* xn_b = g_xn + ((size_t)b * NTOK + 1) * DIMC;

    for (int c = threadIdx.x; c < DIMC; c += 256) {
        float acc = 0.f;
        const float* wc = w + c * 25;
        #pragma unroll
        for (int ky = 0; ky < 5; ky++) {
            int iy = y + ky - 2;
            if (iy < 0 || iy >= FHW) continue;
            #pragma unroll
            for (int kx = 0; kx < 5; kx++) {
                int ix = x + kx - 2;
                if (ix < 0 || ix >= FHW) continue;
                acc += wc[ky * 5 + kx] * xn_b[(size_t)(iy * 32 + ix) * DIMC + c];
            }
        }
        g_dw[(size_t)bpos * DIMC + c] = acc;
    }
}

// ---------------- tf32 tensor-core GEMM (unchanged from R3) ----------------
#define SMS 136

template<bool TB, bool HAS_BIAS>
__global__ void __launch_bounds__(256)
mma_gemm(const float* __restrict__ A, const float* __restrict__ B,
         const float* __restrict__ bias, float* __restrict__ C,
         int M, int N, int K) {
    __shared__ unsigned As[2][16][SMS];
    __shared__ unsigned Bs[2][16][SMS];
    int tid = threadIdx.x;
    int lane = tid & 31, warp = tid >> 5;
    int wm = warp >> 2, wn = warp & 3;
    int g = lane >> 2, t4 = lane & 3;
    int bm = blockIdx.y * 128, bn = blockIdx.x * 128;

    int ar = tid >> 1, ak = (tid & 1) * 8;
    int bk = tid >> 4, bn8 = (tid & 15) * 8;

    float acc[4][4][4];
    #pragma unroll
    for (int i = 0; i < 4; i++)
        #pragma unroll
        for (int j = 0; j < 4; j++)
            #pragma unroll
            for (int r = 0; r < 4; r++) acc[i][j][r] = 0.f;

    unsigned ua[8], ub[8];

    auto gload = [&](int k0) {
        float4 a0 = make_float4(0.f,0.f,0.f,0.f), a1 = a0;
        if (bm + ar < M) {
            const float* p = A + (size_t)(bm + ar) * K + k0 + ak;
            a0 = *(const float4*)p; a1 = *(const float4*)(p + 4);
        }
        ua[0]=f2tf(a0.x); ua[1]=f2tf(a0.y); ua[2]=f2tf(a0.z); ua[3]=f2tf(a0.w);
        ua[4]=f2tf(a1.x); ua[5]=f2tf(a1.y); ua[6]=f2tf(a1.z); ua[7]=f2tf(a1.w);
        if (!TB) {
            const float* p = B + (size_t)(k0 + bk) * N + bn + bn8;
            float4 b0 = *(const float4*)p, b1 = *(const float4*)(p + 4);
            ub[0]=f2tf(b0.x); ub[1]=f2tf(b0.y); ub[2]=f2tf(b0.z); ub[3]=f2tf(b0.w);
            ub[4]=f2tf(b1.x); ub[5]=f2tf(b1.y); ub[6]=f2tf(b1.z); ub[7]=f2tf(b1.w);
        } else {
            const float* p = B + (size_t)(bn + ar) * K + k0 + ak;
            float4 b0 = *(const float4*)p, b1 = *(const float4*)(p + 4);
            ub[0]=f2tf(b0.x); ub[1]=f2tf(b0.y); ub[2]=f2tf(b0.z); ub[3]=f2tf(b0.w);
            ub[4]=f2tf(b1.x); ub[5]=f2tf(b1.y); ub[6]=f2tf(b1.z); ub[7]=f2tf(b1.w);
        }
    };
    auto sstore = [&](int st) {
        #pragma unroll
        for (int i = 0; i < 8; i++) As[st][ak + i][ar] = ua[i];
        if (!TB) {
            *(uint4*)&Bs[st][bk][bn8]     = make_uint4(ub[0], ub[1], ub[2], ub[3]);
            *(uint4*)&Bs[st][bk][bn8 + 4] = make_uint4(ub[4], ub[5], ub[6], ub[7]);
        } else {
            #pragma unroll
            for (int i = 0; i < 8; i++) Bs[st][ak + i][ar] = ub[i];
        }
    };

    gload(0);
    sstore(0);
    __syncthreads();

    int NT = K >> 4;
    for (int t = 0; t < NT; t++) {
        int cur = t & 1;
        if (t + 1 < NT) gload((t + 1) * 16);

        #pragma unroll
        for (int kb = 0; kb < 16; kb += 8) {
            unsigned af[4][4], bf[4][2];
            #pragma unroll
            for (int mi = 0; mi < 4; mi++) {
                int m0 = wm * 64 + mi * 16 + g;
                af[mi][0] = As[cur][kb + t4][m0];
                af[mi][1] = As[cur][kb + t4][m0 + 8];
                af[mi][2] = As[cur][kb + t4 + 4][m0];
                af[mi][3] = As[cur][kb + t4 + 4][m0 + 8];
            }
            #pragma unroll
            for (int ni = 0; ni < 4; ni++) {
                int n0 = wn * 32 + ni * 8 + g;
                bf[ni][0] = Bs[cur][kb + t4][n0];
                bf[ni][1] = Bs[cur][kb + t4 + 4][n0];
            }
            #pragma unroll
            for (int mi = 0; mi < 4; mi++)
                #pragma unroll
                for (int ni = 0; ni < 4; ni++)
                    mma8(acc[mi][ni], af[mi], bf[ni]);
        }

        if (t + 1 < NT) {
            sstore(cur ^ 1);
            __syncthreads();
        }
    }

    #pragma unroll
    for (int mi = 0; mi < 4; mi++) {
        int row0 = bm + wm * 64 + mi * 16 + g;
        int row1 = row0 + 8;
        #pragma unroll
        for (int ni = 0; ni < 4; ni++) {
            int col = bn + wn * 32 + ni * 8 + 2 * t4;
            float b0 = 0.f, b1 = 0.f;
            if (HAS_BIAS) { b0 = bias[col]; b1 = bias[col + 1]; }
            if (row0 < M) {
                float2 v = make_float2(acc[mi][ni][0] + b0, acc[mi][ni][1] + b1);
                *(float2*)(C + (size_t)row0 * N + col) = v;
            }
            if (row1 < M) {
                float2 v = make_float2(acc[mi][ni][2] + b0, acc[mi][ni][3] + b1);
                *(float2*)(C + (size_t)row1 * N + col) = v;
            }
        }
    }
}

// ---------------- q assembly + rope + kv split ----------------
__global__ void assemble_kernel(const float* __restrict__ sinp,
                                const float* __restrict__ cosp) {
    int row = blockIdx.x;
    int b = row / NTOK, n = row % NTOK;
    const float* pwrow = (n > 0) ? (g_pw + ((size_t)b * SP + (n - 1)) * DIMC) : nullptr;
    const float* kvrow = g_kv + (size_t)row * NKV;
    const float* xnrow = g_xn + (size_t)row * DIMC;
    int pos = n - 1;

    for (int c = threadIdx.x; c < DIMC; c += 256) {
        float qv, kv_;
        float vv = kvrow[DIMC + c];
        kv_ = kvrow[c];
        if (n == 0) {
            qv = xnrow[c];
        } else {
            qv = pwrow[c];
            int d = c & 63;
            if (d < NROT) {
                float cs = cosp[pos * NROT + d];
                float sn = sinp[pos * NROT + d];
                float qpart = pwrow[c ^ 1];
                float kpart = kvrow[c ^ 1];
                float qrot = (d & 1) ? qpart : -qpart;
                float krot = (d & 1) ? kpart : -kpart;
                qv  = qv  * cs + qrot * sn;
                kv_ = kv_ * cs + krot * sn;
            }
        }
        g_q[(size_t)row * DIMC + c] = qv;
        g_k[(size_t)row * DIMC + c] = kv_;
        g_v[(size_t)row * DIMC + c] = vv;
    }
}

// ---------------- tensor-core flash attention ----------------
// grid (96, 9), block 256 (8 warps). Block: 128 queries of one (b,h).
// Warp w owns rows w*16..w*16+15. Key tiles of 64, staged in smem (tf32).
#define KTILE 64
#define KSTR  68   // Ks stride: (4g+t4) banks -> conflict-free
#define VSTR  72   // Vs stride: (8t4+g) banks -> conflict-free

__global__ void __launch_bounds__(256)
attn_mma_kernel() {
    __shared__ unsigned Ks[KTILE][KSTR];
    __shared__ unsigned Vs[KTILE][VSTR];

    int bh = blockIdx.x;
    int b = bh / HEADS, h = bh % HEADS;
    int qt0 = blockIdx.y * 128;
    int tid = threadIdx.x, lane = tid & 31, warp = tid >> 5;
    int g = lane >> 2, t4 = lane & 3;

    const float* qb = g_q + ((size_t)b * NTOK) * DIMC + h * DH;
    const float* kb = g_k + ((size_t)b * NTOK) * DIMC + h * DH;
    const float* vb = g_v + ((size_t)b * NTOK) * DIMC + h * DH;

    int r0 = qt0 + warp * 16 + g;    // global query rows for this thread
    int r1 = r0 + 8;

    // ---- Q as A-fragments, scaled, held in registers for the whole block ----
    unsigned aq[8][4];
    #pragma unroll
    for (int kk = 0; kk < 8; kk++) {
        float x0 = 0.f, x1 = 0.f, x2 = 0.f, x3 = 0.f;
        if (r0 < NTOK) {
            x0 = qb[(size_t)r0 * DIMC + kk * 8 + t4];
            x2 = qb[(size_t)r0 * DIMC + kk * 8 + t4 + 4];
        }
        if (r1 < NTOK) {
            x1 = qb[(size_t)r1 * DIMC + kk * 8 + t4];
            x3 = qb[(size_t)r1 * DIMC + kk * 8 + t4 + 4];
        }
        aq[kk][0] = f2tf(x0 * 0.125f);
        aq[kk][1] = f2tf(x1 * 0.125f);
        aq[kk][2] = f2tf(x2 * 0.125f);
        aq[kk][3] = f2tf(x3 * 0.125f);
    }

    float o[8][4];
    #pragma unroll
    for (int i = 0; i < 8; i++)
        #pragma unroll
        for (int j = 0; j < 4; j++) o[i][j] = 0.f;
    float m0 = -1e30f, m1 = -1e30f, l0 = 0.f, l1 = 0.f;

    for (int kt0 = 0; kt0 < NTOK; kt0 += KTILE) {
        __syncthreads();
        // ---- stage K,V tile (tf32) ----
        #pragma unroll
        for (int lp = 0; lp < 8; lp++) {
            int pos = tid + lp * 256;           // 0..2047 over 2 iters of 8? no:
            // 64 rows * 16 float4 = 1024 slots; 256 threads -> 4 slots each.
            if (lp >= 4) break;
            pos = tid + lp * 256;
            int row = pos >> 4, c4 = pos & 15;
            int key = kt0 + row;
            float4 kk4 = make_float4(0.f,0.f,0.f,0.f), vv4 = kk4;
            if (key < NTOK) {
                kk4 = *(const float4*)(kb + (size_t)key * DIMC + c4 * 4);
                vv4 = *(const float4*)(vb + (size_t)key * DIMC + c4 * 4);
            }
            *(uint4*)&Ks[row][c4 * 4] =
                make_uint4(f2tf(kk4.x), f2tf(kk4.y), f2tf(kk4.z), f2tf(kk4.w));
            *(uint4*)&Vs[row][c4 * 4] =
                make_uint4(f2tf(vv4.x), f2tf(vv4.y), f2tf(vv4.z), f2tf(vv4.w));
        }
        __syncthreads();

        // ---- S = Q @ K^T : sc[ni] covers keys kt0+ni*8..+7 ----
        float sc[8][4];
        #pragma unroll
        for (int i = 0; i < 8; i++)
            #pragma unroll
            for (int j = 0; j < 4; j++) sc[i][j] = 0.f;

        #pragma unroll
        for (int kk = 0; kk < 8; kk++) {
            #pragma unroll
            for (int ni = 0; ni < 8; ni++) {
                unsigned bf[2];
                bf[0] = Ks[ni * 8 + g][kk * 8 + t4];
                bf[1] = Ks[ni * 8 + g][kk * 8 + t4 + 4];
                mma8(sc[ni], aq[kk], bf);
            }
        }

        // ---- mask invalid keys (only last tile) ----
        if (kt0 + KTILE > NTOK) {
            #pragma unroll
            for (int ni = 0; ni < 8; ni++) {
                int key = kt0 + ni * 8 + 2 * t4;
                if (key     >= NTOK) { sc[ni][0] = -1e30f; sc[ni][2] = -1e30f; }
                if (key + 1 >= NTOK) { sc[ni][1] = -1e30f; sc[ni][3] = -1e30f; }
            }
        }

        // ---- online softmax ----
        float mx0 = -1e30f, mx1 = -1e30f;
        #pragma unroll
        for (int ni = 0; ni < 8; ni++) {
            mx0 = fmaxf(mx0, fmaxf(sc[ni][0], sc[ni][1]));
            mx1 = fmaxf(mx1, fmaxf(sc[ni][2], sc[ni][3]));
        }
        mx0 = fmaxf(mx0, __shfl_xor_sync(0xffffffffu, mx0, 1));
        mx0 = fmaxf(mx0, __shfl_xor_sync(0xffffffffu, mx0, 2));
        mx1 = fmaxf(mx1, __shfl_xor_sync(0xffffffffu, mx1, 1));
        mx1 = fmaxf(mx1, __shfl_xor_sync(0xffffffffu, mx1, 2));
        float nm0 = fmaxf(m0, mx0), nm1 = fmaxf(m1, mx1);
        float cor0 = __expf(m0 - nm0), cor1 = __expf(m1 - nm1);
        m0 = nm0; m1 = nm1;

        float ps0 = 0.f, ps1 = 0.f;
        #pragma unroll
        for (int ni = 0; ni < 8; ni++) {
            sc[ni][0] = __expf(sc[ni][0] - nm0); ps0 += sc[ni][0];
            sc[ni][1] = __expf(sc[ni][1] - nm0); ps0 += sc[ni][1];
            sc[ni][2] = __expf(sc[ni][2] - nm1); ps1 += sc[ni][2];
            sc[ni][3] = __expf(sc[ni][3] - nm1); ps1 += sc[ni][3];
        }
        l0 = l0 * cor0 + ps0;
        l1 = l1 * cor1 + ps1;
        #pragma unroll
        for (int ni = 0; ni < 8; ni++) {
            o[ni][0] *= cor0; o[ni][1] *= cor0;
            o[ni][2] *= cor1; o[ni][3] *= cor1;
        }

        // ---- O += P @ V ;  P C-frag -> A-frag via quad shuffles ----
        int srcA = (g << 2) | (t4 >> 1);
        int srcB = srcA + 2;
        bool hi = t4 & 1;
        #pragma unroll
        for (int kc = 0; kc < 8; kc++) {
            float v00 = __shfl_sync(0xffffffffu, sc[kc][0], srcA);
            float v01 = __shfl_sync(0xffffffffu, sc[kc][1], srcA);
            float v10 = __shfl_sync(0xffffffffu, sc[kc][2], srcA);
            float v11 = __shfl_sync(0xffffffffu, sc[kc][3], srcA);
            float w00 = __shfl_sync(0xffffffffu, sc[kc][0], srcB);
            float w01 = __shfl_sync(0xffffffffu, sc[kc][1], srcB);
            float w10 = __shfl_sync(0xffffffffu, sc[kc][2], srcB);
            float w11 = __shfl_sync(0xffffffffu, sc[kc][3], srcB);
            unsigned ap[4];
            ap[0] = f2tf(hi ? v01 : v00);   // (row g,   k=t4)
            ap[1] = f2tf(hi ? v11 : v10);   // (row g+8, k=t4)
            ap[2] = f2tf(hi ? w01 : w00);   // (row g,   k=t4+4)
            ap[3] = f2tf(hi ? w11 : w10);   // (row g+8, k=t4+4)
            #pragma unroll
            for (int ni = 0; ni < 8; ni++) {
                unsigned bf[2];
                bf[0] = Vs[kc * 8 + t4][ni * 8 + g];
                bf[1] = Vs[kc * 8 + t4 + 4][ni * 8 + g];
                mma8(o[ni], ap, bf);
            }
        }
    }

    // ---- finalize: quad-sum l, normalize, store ----
    l0 += __shfl_xor_sync(0xffffffffu, l0, 1);
    l0 += __shfl_xor_sync(0xffffffffu, l0, 2);
    l1 += __shfl_xor_sync(0xffffffffu, l1, 1);
    l1 += __shfl_xor_sync(0xffffffffu, l1, 2);
    float inv0 = 1.f / l0, inv1 = 1.f / l1;

    if (r0 < NTOK) {
        float* op = g_ao + ((size_t)b * NTOK + r0) * DIMC + h * DH;
        #pragma unroll
        for (int ni = 0; ni < 8; ni++)
            *(float2*)(op + ni * 8 + 2 * t4) =
                make_float2(o[ni][0] * inv0, o[ni][1] * inv0);
    }
    if (r1 < NTOK) {
        float* op = g_ao + ((size_t)b * NTOK + r1) * DIMC + h * DH;
        #pragma unroll
        for (int ni = 0; ni < 8; ni++)
            *(float2*)(op + ni * 8 + 2 * t4) =
                make_float2(o[ni][2] * inv1, o[ni][3] * inv1);
    }
}

// ---------------- launch ----------------
extern "C" void kernel_launch(void* const* d_in, const int* in_sizes, int n_in,
                              void* d_out, int out_size) {
    const float* x     = (const float*)d_in[0];
    const float* sinp  = (const float*)d_in[1];
    const float* cosp  = (const float*)d_in[2];
    const float* ln_g  = (const float*)d_in[3];
    const float* ln_b  = (const float*)d_in[4];
    const float* dw_w  = (const float*)d_in[5];
    const float* pw_w  = (const float*)d_in[6];
    const float* kv_w  = (const float*)d_in[7];
    const float* out_w = (const float*)d_in[8];
    const float* out_b = (const float*)d_in[9];
    float* out = (float*)d_out;

    float *p_xn, *p_dw, *p_pw, *p_kv, *p_ao;
    cudaGetSymbolAddress((void**)&p_xn, g_xn);
    cudaGetSymbolAddress((void**)&p_dw, g_dw);
    cudaGetSymbolAddress((void**)&p_pw, g_pw);
    cudaGetSymbolAddress((void**)&p_kv, g_kv);
    cudaGetSymbolAddress((void**)&p_ao, g_ao);

    ln_kernel<<<BB * NTOK, 256>>>(x, ln_g, ln_b);
    dw_kernel<<<BB * SP, 256>>>(dw_w);
    mma_gemm<true, false><<<dim3(DIMC / 128, (BB * SP) / 128), 256>>>(
        p_dw, pw_w, nullptr, p_pw, BB * SP, DIMC, DIMC);
    mma_gemm<false, false><<<dim3(NKV / 128, (BB * NTOK + 127) / 128), 256>>>(
        p_xn, kv_w, nullptr, p_kv, BB * NTOK, NKV, DIMC);
    assemble_kernel<<<BB * NTOK, 256>>>(sinp, cosp);
    attn_mma_kernel<<<dim3(BB * HEADS, (NTOK + 127) / 128), 256>>>();
    mma_gemm<false, true><<<dim3(DIMC / 128, (BB * NTOK + 127) / 128), 256>>>(
        p_ao, out_w, out_b, out, BB * NTOK, DIMC, DIMC);
}

// round 5
// speedup vs baseline: 3.1432x; 1.1643x over previous
#include <cuda_runtime.h>
#include <math.h>

// ---------------- problem constants ----------------
#define BB    8
#define NTOK  1025
#define SP    1024
#define FHW   32
#define DIMC  768
#define NKV   1536
#define HEADS 12
#define DH    64
#define NROT  32

// ---------------- scratch ----------------
__device__ float g_xn[BB*NTOK*DIMC];
__device__ float g_dw[BB*SP*DIMC];
__device__ float g_pw[BB*SP*DIMC];
__device__ float g_kv[BB*NTOK*NKV];
__device__ float g_q [BB*NTOK*DIMC];
__device__ float g_k [BB*NTOK*DIMC];
__device__ float g_v [BB*NTOK*DIMC];
__device__ float g_ao[BB*NTOK*DIMC];
// tf32-rounded weights
__device__ float g_pww[DIMC*DIMC];
__device__ float g_kvw[DIMC*NKV];
__device__ float g_oww[DIMC*DIMC];

// ---------------- tf32 helpers ----------------
__device__ __forceinline__ unsigned f2tf(float f) {
    unsigned r;
    asm("cvt.rna.tf32.f32 %0, %1;" : "=r"(r) : "f"(f));
    return r;
}
__device__ __forceinline__ float tfr(float f) {      // round fp32 -> tf32-exact fp32
    return __uint_as_float(f2tf(f));
}
__device__ __forceinline__ void mma8(float* c, const unsigned* a, const unsigned* b) {
    asm volatile(
        "mma.sync.aligned.m16n8k8.row.col.f32.tf32.tf32.f32 "
        "{%0,%1,%2,%3}, {%4,%5,%6,%7}, {%8,%9}, {%0,%1,%2,%3};"
        : "+f"(c[0]), "+f"(c[1]), "+f"(c[2]), "+f"(c[3])
        : "r"(a[0]), "r"(a[1]), "r"(a[2]), "r"(a[3]), "r"(b[0]), "r"(b[1]));
}
__device__ __forceinline__ void cp16(void* dst, const void* src, bool valid) {
    unsigned d = (unsigned)__cvta_generic_to_shared(dst);
    int sz = valid ? 16 : 0;
    asm volatile("cp.async.ca.shared.global [%0], [%1], 16, %2;\n"
                 :: "r"(d), "l"(src), "r"(sz));
}
__device__ __forceinline__ void cp_commit() {
    asm volatile("cp.async.commit_group;\n");
}
__device__ __forceinline__ void cp_wait1() {
    asm volatile("cp.async.wait_group 1;\n");
}

// ---------------- weight rounding prepass ----------------
__global__ void round_w_kernel(const float* __restrict__ pw,
                               const float* __restrict__ kv,
                               const float* __restrict__ ow) {
    int i = blockIdx.x * 256 + threadIdx.x;
    if (i < DIMC*DIMC) g_pww[i] = tfr(pw[i]);
    if (i < DIMC*NKV)  g_kvw[i] = tfr(kv[i]);
    if (i < DIMC*DIMC) g_oww[i] = tfr(ow[i]);
}

// ---------------- layernorm (tf32-rounded output) ----------------
__global__ void ln_kernel(const float* __restrict__ x,
                          const float* __restrict__ gamma,
                          const float* __restrict__ beta) {
    int row = blockIdx.x;
    int t = threadIdx.x;
    const float* xr = x + (size_t)row * DIMC;

    float v0 = xr[t], v1 = xr[t + 256], v2 = xr[t + 512];
    float s  = v0 + v1 + v2;
    float s2 = v0*v0 + v1*v1 + v2*v2;

    int lane = t & 31, w = t >> 5;
    #pragma unroll
    for (int o = 16; o; o >>= 1) {
        s  += __shfl_xor_sync(0xffffffffu, s,  o);
        s2 += __shfl_xor_sync(0xffffffffu, s2, o);
    }
    __shared__ float shs[8], shs2[8];
    if (lane == 0) { shs[w] = s; shs2[w] = s2; }
    __syncthreads();
    if (w == 0) {
        float a  = (lane < 8) ? shs[lane]  : 0.f;
        float a2 = (lane < 8) ? shs2[lane] : 0.f;
        #pragma unroll
        for (int o = 4; o; o >>= 1) {
            a  += __shfl_xor_sync(0xffffffffu, a,  o);
            a2 += __shfl_xor_sync(0xffffffffu, a2, o);
        }
        if (lane == 0) { shs[0] = a; shs2[0] = a2; }
    }
    __syncthreads();
    float mu  = shs[0] * (1.f / DIMC);
    float var = shs2[0] * (1.f / DIMC) - mu * mu;
    float r = rsqrtf(var + 1e-5f);

    float* o = g_xn + (size_t)row * DIMC;
    o[t]       = tfr((v0 - mu) * r * gamma[t]       + beta[t]);
    o[t + 256] = tfr((v1 - mu) * r * gamma[t + 256] + beta[t + 256]);
    o[t + 512] = tfr((v2 - mu) * r * gamma[t + 512] + beta[t + 512]);
}

// ---------------- depthwise 5x5 conv, smem-tiled ----------------
// block: 16 channels x 8 rows x 32 cols of one batch. grid (48, 4, 8).
__global__ void __launch_bounds__(256) dw_kernel2(const float* __restrict__ w) {
    __shared__ float S[12][36][16];
    __shared__ float Ws[16][25];
    int c0 = blockIdx.x * 16;
    int y0 = blockIdx.y * 8;
    int b  = blockIdx.z;
    int tid = threadIdx.x;
    const float* xn_b = g_xn + ((size_t)b * NTOK + 1) * DIMC;

    for (int i = tid; i < 16 * 25; i += 256) {
        int c = i / 25, kk = i % 25;
        Ws[c][kk] = w[(c0 + c) * 25 + kk];
    }
    for (int i = tid; i < 12 * 36 * 16; i += 256) {
        int row = i / 576, rem = i % 576;
        int col = rem / 16, ch = rem % 16;
        int gy = y0 + row - 2, gx = col - 2;
        float v = 0.f;
        if (gy >= 0 && gy < FHW && gx >= 0 && gx < FHW)
            v = xn_b[(size_t)(gy * 32 + gx) * DIMC + c0 + ch];
        S[row][col][ch] = v;
    }
    __syncthreads();

    for (int k = 0; k < 16; k++) {
        int oi = k * 256 + tid;
        int oc = oi & 15;
        int ox = (oi >> 4) & 31;
        int oy = oi >> 9;
        float acc = 0.f;
        #pragma unroll
        for (int ky = 0; ky < 5; ky++)
            #pragma unroll
            for (int kx = 0; kx < 5; kx++)
                acc = fmaf(Ws[oc][ky * 5 + kx], S[oy + ky][ox + kx][oc], acc);
        g_dw[((size_t)b * SP + (y0 + oy) * 32 + ox) * DIMC + c0 + oc] = tfr(acc);
    }
}

// ---------------- tf32 MMA GEMM v2: cp.async 2-stage, no cvt in loop --------
// Inputs MUST be tf32-exact fp32. TB=false: B is KxN. TB=true: B is NxK.
#define ASTR 20    // [row][k] stride (words): conflict-free (g*20+t4)%32
#define BSTR 136   // [k][n] stride (words): conflict-free (t4*8+g)

template<bool TB, bool HAS_BIAS>
__global__ void __launch_bounds__(256)
mma_gemm2(const float* __restrict__ A, const float* __restrict__ B,
          const float* __restrict__ bias, float* __restrict__ C,
          int M, int N, int K) {
    __shared__ __align__(16) float As[2][128][ASTR];
    constexpr int BW = TB ? 128 * ASTR : 16 * BSTR;
    __shared__ __align__(16) float Bs[2][BW];

    int tid = threadIdx.x;
    int lane = tid & 31, warp = tid >> 5;
    int wm = warp >> 2, wn = warp & 3;
    int g = lane >> 2, t4 = lane & 3;
    int bm = blockIdx.y * 128, bn = blockIdx.x * 128;

    int ar = tid >> 1, ak = (tid & 1) * 8;
    int bk = tid >> 4, n8 = (tid & 15) * 8;

    auto issue = [&](int st, int k0) {
        const float* ga = A + (size_t)(bm + ar) * K + k0 + ak;
        bool av = (bm + ar) < M;
        cp16(&As[st][ar][ak],     ga,     av);
        cp16(&As[st][ar][ak + 4], ga + 4, av);
        if (TB) {
            const float* gb = B + (size_t)(bn + ar) * K + k0 + ak;
            cp16(&Bs[st][ar * ASTR + ak],     gb,     true);
            cp16(&Bs[st][ar * ASTR + ak + 4], gb + 4, true);
        } else {
            const float* gb = B + (size_t)(k0 + bk) * N + bn + n8;
            cp16(&Bs[st][bk * BSTR + n8],     gb,     true);
            cp16(&Bs[st][bk * BSTR + n8 + 4], gb + 4, true);
        }
    };

    float acc[4][4][4];
    #pragma unroll
    for (int i = 0; i < 4; i++)
        #pragma unroll
        for (int j = 0; j < 4; j++)
            #pragma unroll
            for (int r = 0; r < 4; r++) acc[i][j][r] = 0.f;

    issue(0, 0);
    cp_commit();

    int NT = K >> 4;
    for (int t = 0; t < NT; t++) {
        int cur = t & 1;
        if (t > 0) __syncthreads();
        if (t + 1 < NT) issue(cur ^ 1, (t + 1) * 16);
        cp_commit();
        cp_wait1();
        __syncthreads();

        #pragma unroll
        for (int kb = 0; kb < 16; kb += 8) {
            unsigned af[4][4], bf[4][2];
            #pragma unroll
            for (int mi = 0; mi < 4; mi++) {
                int m0 = wm * 64 + mi * 16 + g;
                af[mi][0] = __float_as_uint(As[cur][m0][kb + t4]);
                af[mi][1] = __float_as_uint(As[cur][m0 + 8][kb + t4]);
                af[mi][2] = __float_as_uint(As[cur][m0][kb + t4 + 4]);
                af[mi][3] = __float_as_uint(As[cur][m0 + 8][kb + t4 + 4]);
            }
            #pragma unroll
            for (int ni = 0; ni < 4; ni++) {
                int n0 = wn * 32 + ni * 8 + g;
                if (TB) {
                    bf[ni][0] = __float_as_uint(Bs[cur][n0 * ASTR + kb + t4]);
                    bf[ni][1] = __float_as_uint(Bs[cur][n0 * ASTR + kb + t4 + 4]);
                } else {
                    bf[ni][0] = __float_as_uint(Bs[cur][(kb + t4) * BSTR + n0]);
                    bf[ni][1] = __float_as_uint(Bs[cur][(kb + t4 + 4) * BSTR + n0]);
                }
            }
            #pragma unroll
            for (int mi = 0; mi < 4; mi++)
                #pragma unroll
                for (int ni = 0; ni < 4; ni++)
                    mma8(acc[mi][ni], af[mi], bf[ni]);
        }
    }

    #pragma unroll
    for (int mi = 0; mi < 4; mi++) {
        int row0 = bm + wm * 64 + mi * 16 + g;
        int row1 = row0 + 8;
        #pragma unroll
        for (int ni = 0; ni < 4; ni++) {
            int col = bn + wn * 32 + ni * 8 + 2 * t4;
            float b0 = 0.f, b1 = 0.f;
            if (HAS_BIAS) { b0 = bias[col]; b1 = bias[col + 1]; }
            if (row0 < M) {
                float2 v = make_float2(acc[mi][ni][0] + b0, acc[mi][ni][1] + b1);
                *(float2*)(C + (size_t)row0 * N + col) = v;
            }
            if (row1 < M) {
                float2 v = make_float2(acc[mi][ni][2] + b0, acc[mi][ni][3] + b1);
                *(float2*)(C + (size_t)row1 * N + col) = v;
            }
        }
    }
}

// ---------------- q assembly + rope + kv split (tf32-rounded outputs) -------
__global__ void assemble_kernel(const float* __restrict__ sinp,
                                const float* __restrict__ cosp) {
    int row = blockIdx.x;
    int b = row / NTOK, n = row % NTOK;
    const float* pwrow = (n > 0) ? (g_pw + ((size_t)b * SP + (n - 1)) * DIMC) : nullptr;
    const float* kvrow = g_kv + (size_t)row * NKV;
    const float* xnrow = g_xn + (size_t)row * DIMC;
    int pos = n - 1;

    for (int c = threadIdx.x; c < DIMC; c += 256) {
        float qv, kv_;
        float vv = kvrow[DIMC + c];
        kv_ = kvrow[c];
        if (n == 0) {
            qv = xnrow[c];
        } else {
            qv = pwrow[c];
            int d = c & 63;
            if (d < NROT) {
                float cs = cosp[pos * NROT + d];
                float sn = sinp[pos * NROT + d];
                float qpart = pwrow[c ^ 1];
                float kpart = kvrow[c ^ 1];
                float qrot = (d & 1) ? qpart : -qpart;
                float krot = (d & 1) ? kpart : -kpart;
                qv  = qv  * cs + qrot * sn;
                kv_ = kv_ * cs + krot * sn;
            }
        }
        g_q[(size_t)row * DIMC + c] = tfr(qv);
        g_k[(size_t)row * DIMC + c] = tfr(kv_);
        g_v[(size_t)row * DIMC + c] = tfr(vv);
    }
}

// ---------------- tensor-core flash attention (cvt-free staging) ------------
#define KTILE 64
#define KSTR  68
#define VSTR  72

__global__ void __launch_bounds__(256)
attn_mma_kernel() {
    __shared__ unsigned Ks[KTILE][KSTR];
    __shared__ unsigned Vs[KTILE][VSTR];

    int bh = blockIdx.x;
    int b = bh / HEADS, h = bh % HEADS;
    int qt0 = blockIdx.y * 128;
    int tid = threadIdx.x, lane = tid & 31, warp = tid >> 5;
    int g = lane >> 2, t4 = lane & 3;

    const float* qb = g_q + ((size_t)b * NTOK) * DIMC + h * DH;
    const float* kb = g_k + ((size_t)b * NTOK) * DIMC + h * DH;
    const float* vb = g_v + ((size_t)b * NTOK) * DIMC + h * DH;

    int r0 = qt0 + warp * 16 + g;
    int r1 = r0 + 8;

    // Q as A-fragments (inputs pre-rounded; *0.125 is exact in tf32)
    unsigned aq[8][4];
    #pragma unroll
    for (int kk = 0; kk < 8; kk++) {
        float x0 = 0.f, x1 = 0.f, x2 = 0.f, x3 = 0.f;
        if (r0 < NTOK) {
            x0 = qb[(size_t)r0 * DIMC + kk * 8 + t4];
            x2 = qb[(size_t)r0 * DIMC + kk * 8 + t4 + 4];
        }
        if (r1 < NTOK) {
            x1 = qb[(size_t)r1 * DIMC + kk * 8 + t4];
            x3 = qb[(size_t)r1 * DIMC + kk * 8 + t4 + 4];
        }
        aq[kk][0] = __float_as_uint(x0 * 0.125f);
        aq[kk][1] = __float_as_uint(x1 * 0.125f);
        aq[kk][2] = __float_as_uint(x2 * 0.125f);
        aq[kk][3] = __float_as_uint(x3 * 0.125f);
    }

    float o[8][4];
    #pragma unroll
    for (int i = 0; i < 8; i++)
        #pragma unroll
        for (int j = 0; j < 4; j++) o[i][j] = 0.f;
    float m0 = -1e30f, m1 = -1e30f, l0 = 0.f, l1 = 0.f;

    for (int kt0 = 0; kt0 < NTOK; kt0 += KTILE) {
        __syncthreads();
        #pragma unroll
        for (int lp = 0; lp < 4; lp++) {
            int pos = tid + lp * 256;
            int row = pos >> 4, c4 = pos & 15;
            int key = kt0 + row;
            uint4 kk4 = make_uint4(0u, 0u, 0u, 0u), vv4 = kk4;
            if (key < NTOK) {
                kk4 = *(const uint4*)(kb + (size_t)key * DIMC + c4 * 4);
                vv4 = *(const uint4*)(vb + (size_t)key * DIMC + c4 * 4);
            }
            *(uint4*)&Ks[row][c4 * 4] = kk4;
            *(uint4*)&Vs[row][c4 * 4] = vv4;
        }
        __syncthreads();

        float sc[8][4];
        #pragma unroll
        for (int i = 0; i < 8; i++)
            #pragma unroll
            for (int j = 0; j < 4; j++) sc[i][j] = 0.f;

        #pragma unroll
        for (int kk = 0; kk < 8; kk++) {
            #pragma unroll
            for (int ni = 0; ni < 8; ni++) {
                unsigned bf[2];
                bf[0] = Ks[ni * 8 + g][kk * 8 + t4];
                bf[1] = Ks[ni * 8 + g][kk * 8 + t4 + 4];
                mma8(sc[ni], aq[kk], bf);
            }
        }

        if (kt0 + KTILE > NTOK) {
            #pragma unroll
            for (int ni = 0; ni < 8; ni++) {
                int key = kt0 + ni * 8 + 2 * t4;
                if (key     >= NTOK) { sc[ni][0] = -1e30f; sc[ni][2] = -1e30f; }
                if (key + 1 >= NTOK) { sc[ni][1] = -1e30f; sc[ni][3] = -1e30f; }
            }
        }

        float mx0 = -1e30f, mx1 = -1e30f;
        #pragma unroll
        for (int ni = 0; ni < 8; ni++) {
            mx0 = fmaxf(mx0, fmaxf(sc[ni][0], sc[ni][1]));
            mx1 = fmaxf(mx1, fmaxf(sc[ni][2], sc[ni][3]));
        }
        mx0 = fmaxf(mx0, __shfl_xor_sync(0xffffffffu, mx0, 1));
        mx0 = fmaxf(mx0, __shfl_xor_sync(0xffffffffu, mx0, 2));
        mx1 = fmaxf(mx1, __shfl_xor_sync(0xffffffffu, mx1, 1));
        mx1 = fmaxf(mx1, __shfl_xor_sync(0xffffffffu, mx1, 2));
        float nm0 = fmaxf(m0, mx0), nm1 = fmaxf(m1, mx1);
        float cor0 = __expf(m0 - nm0), cor1 = __expf(m1 - nm1);
        m0 = nm0; m1 = nm1;

        float ps0 = 0.f, ps1 = 0.f;
        #pragma unroll
        for (int ni = 0; ni < 8; ni++) {
            sc[ni][0] = __expf(sc[ni][0] - nm0); ps0 += sc[ni][0];
            sc[ni][1] = __expf(sc[ni][1] - nm0); ps0 += sc[ni][1];
            sc[ni][2] = __expf(sc[ni][2] - nm1); ps1 += sc[ni][2];
            sc[ni][3] = __expf(sc[ni][3] - nm1); ps1 += sc[ni][3];
        }
        l0 = l0 * cor0 + ps0;
        l1 = l1 * cor1 + ps1;
        #pragma unroll
        for (int ni = 0; ni < 8; ni++) {
            o[ni][0] *= cor0; o[ni][1] *= cor0;
            o[ni][2] *= cor1; o[ni][3] *= cor1;
        }

        int srcA = (g << 2) | (t4 >> 1);
        int srcB = srcA + 2;
        bool hi = t4 & 1;
        #pragma unroll
        for (int kc = 0; kc < 8; kc++) {
            float v00 = __shfl_sync(0xffffffffu, sc[kc][0], srcA);
            float v01 = __shfl_sync(0xffffffffu, sc[kc][1], srcA);
            float v10 = __shfl_sync(0xffffffffu, sc[kc][2], srcA);
            float v11 = __shfl_sync(0xffffffffu, sc[kc][3], srcA);
            float w00 = __shfl_sync(0xffffffffu, sc[kc][0], srcB);
            float w01 = __shfl_sync(0xffffffffu, sc[kc][1], srcB);
            float w10 = __shfl_sync(0xffffffffu, sc[kc][2], srcB);
            float w11 = __shfl_sync(0xffffffffu, sc[kc][3], srcB);
            unsigned ap[4];
            ap[0] = f2tf(hi ? v01 : v00);
            ap[1] = f2tf(hi ? v11 : v10);
            ap[2] = f2tf(hi ? w01 : w00);
            ap[3] = f2tf(hi ? w11 : w10);
            #pragma unroll
            for (int ni = 0; ni < 8; ni++) {
                unsigned bf[2];
                bf[0] = Vs[kc * 8 + t4][ni * 8 + g];
                bf[1] = Vs[kc * 8 + t4 + 4][ni * 8 + g];
                mma8(o[ni], ap, bf);
            }
        }
    }

    l0 += __shfl_xor_sync(0xffffffffu, l0, 1);
    l0 += __shfl_xor_sync(0xffffffffu, l0, 2);
    l1 += __shfl_xor_sync(0xffffffffu, l1, 1);
    l1 += __shfl_xor_sync(0xffffffffu, l1, 2);
    float inv0 = 1.f / l0, inv1 = 1.f / l1;

    if (r0 < NTOK) {
        float* op = g_ao + ((size_t)b * NTOK + r0) * DIMC + h * DH;
        #pragma unroll
        for (int ni = 0; ni < 8; ni++)
            *(float2*)(op + ni * 8 + 2 * t4) =
                make_float2(tfr(o[ni][0] * inv0), tfr(o[ni][1] * inv0));
    }
    if (r1 < NTOK) {
        float* op = g_ao + ((size_t)b * NTOK + r1) * DIMC + h * DH;
        #pragma unroll
        for (int ni = 0; ni < 8; ni++)
            *(float2*)(op + ni * 8 + 2 * t4) =
                make_float2(tfr(o[ni][2] * inv1), tfr(o[ni][3] * inv1));
    }
}

// ---------------- launch ----------------
extern "C" void kernel_launch(void* const* d_in, const int* in_sizes, int n_in,
                              void* d_out, int out_size) {
    const float* x     = (const float*)d_in[0];
    const float* sinp  = (const float*)d_in[1];
    const float* cosp  = (const float*)d_in[2];
    const float* ln_g  = (const float*)d_in[3];
    const float* ln_b  = (const float*)d_in[4];
    const float* dw_w  = (const float*)d_in[5];
    const float* pw_w  = (const float*)d_in[6];
    const float* kv_w  = (const float*)d_in[7];
    const float* out_w = (const float*)d_in[8];
    const float* out_b = (const float*)d_in[9];
    float* out = (float*)d_out;

    float *p_dw, *p_pw, *p_xn, *p_kv, *p_ao, *p_pww, *p_kvw, *p_oww;
    cudaGetSymbolAddress((void**)&p_xn, g_xn);
    cudaGetSymbolAddress((void**)&p_dw, g_dw);
    cudaGetSymbolAddress((void**)&p_pw, g_pw);
    cudaGetSymbolAddress((void**)&p_kv, g_kv);
    cudaGetSymbolAddress((void**)&p_ao, g_ao);
    cudaGetSymbolAddress((void**)&p_pww, g_pww);
    cudaGetSymbolAddress((void**)&p_kvw, g_kvw);
    cudaGetSymbolAddress((void**)&p_oww, g_oww);

    round_w_kernel<<<(DIMC * NKV + 255) / 256, 256>>>(pw_w, kv_w, out_w);
    ln_kernel<<<BB * NTOK, 256>>>(x, ln_g, ln_b);
    dw_kernel2<<<dim3(DIMC / 16, 4, BB), 256>>>(dw_w);
    // pointwise conv: g_pw = g_dw @ pw_w^T   (M=8192, N=768, K=768)
    mma_gemm2<true, false><<<dim3(DIMC / 128, (BB * SP) / 128), 256>>>(
        p_dw, p_pww, nullptr, p_pw, BB * SP, DIMC, DIMC);
    // kv gemm: g_kv = g_xn @ kv_w            (M=8200, N=1536, K=768)
    mma_gemm2<false, false><<<dim3(NKV / 128, (BB * NTOK + 127) / 128), 256>>>(
        p_xn, p_kvw, nullptr, p_kv, BB * NTOK, NKV, DIMC);
    assemble_kernel<<<BB * NTOK, 256>>>(sinp, cosp);
    attn_mma_kernel<<<dim3(BB * HEADS, (NTOK + 127) / 128), 256>>>();
    // output projection + bias               (M=8200, N=768, K=768)
    mma_gemm2<false, true><<<dim3(DIMC / 128, (BB * NTOK + 127) / 128), 256>>>(
        p_ao, p_oww, out_b, out, BB * NTOK, DIMC, DIMC);
}

// round 6
// speedup vs baseline: 3.2391x; 1.0305x over previous
#include <cuda_runtime.h>
#include <math.h>

// ---------------- problem constants ----------------
#define BB    8
#define NTOK  1025
#define SP    1024
#define FHW   32
#define DIMC  768
#define NKV   1536
#define HEADS 12
#define DH    64
#define NROT  32

// ---------------- scratch ----------------
__device__ float g_xn[BB*NTOK*DIMC];
__device__ float g_dw[BB*SP*DIMC];
__device__ float g_pw[BB*SP*DIMC];
__device__ float g_kv[BB*NTOK*NKV];
__device__ float g_q [BB*NTOK*DIMC];
__device__ float g_k [BB*NTOK*DIMC];
__device__ float g_v [BB*NTOK*DIMC];
__device__ float g_ao[BB*NTOK*DIMC];
__device__ float g_pww[DIMC*DIMC];
__device__ float g_kvw[DIMC*NKV];
__device__ float g_oww[DIMC*DIMC];

// ---------------- tf32 / cp.async helpers ----------------
__device__ __forceinline__ unsigned f2tf(float f) {
    unsigned r;
    asm("cvt.rna.tf32.f32 %0, %1;" : "=r"(r) : "f"(f));
    return r;
}
__device__ __forceinline__ float tfr(float f) {
    return __uint_as_float(f2tf(f));
}
__device__ __forceinline__ void mma8(float* c, const unsigned* a, const unsigned* b) {
    asm volatile(
        "mma.sync.aligned.m16n8k8.row.col.f32.tf32.tf32.f32 "
        "{%0,%1,%2,%3}, {%4,%5,%6,%7}, {%8,%9}, {%0,%1,%2,%3};"
        : "+f"(c[0]), "+f"(c[1]), "+f"(c[2]), "+f"(c[3])
        : "r"(a[0]), "r"(a[1]), "r"(a[2]), "r"(a[3]), "r"(b[0]), "r"(b[1]));
}
__device__ __forceinline__ void cp16(void* dst, const void* src, bool valid) {
    unsigned d = (unsigned)__cvta_generic_to_shared(dst);
    int sz = valid ? 16 : 0;           // sz=0 -> zero-fill 16B, no src read
    asm volatile("cp.async.ca.shared.global [%0], [%1], 16, %2;\n"
                 :: "r"(d), "l"(src), "r"(sz));
}
__device__ __forceinline__ void cp_commit() {
    asm volatile("cp.async.commit_group;\n");
}
template<int N>
__device__ __forceinline__ void cp_waitg() {
    asm volatile("cp.async.wait_group %0;\n" :: "n"(N));
}

// ---------------- weight rounding prepass ----------------
__global__ void round_w_kernel(const float* __restrict__ pw,
                               const float* __restrict__ kv,
                               const float* __restrict__ ow) {
    int i = blockIdx.x * 256 + threadIdx.x;
    if (i < DIMC*DIMC) g_pww[i] = tfr(pw[i]);
    if (i < DIMC*NKV)  g_kvw[i] = tfr(kv[i]);
    if (i < DIMC*DIMC) g_oww[i] = tfr(ow[i]);
}

// ---------------- layernorm ----------------
__global__ void ln_kernel(const float* __restrict__ x,
                          const float* __restrict__ gamma,
                          const float* __restrict__ beta) {
    int row = blockIdx.x;
    int t = threadIdx.x;
    const float* xr = x + (size_t)row * DIMC;

    float v0 = xr[t], v1 = xr[t + 256], v2 = xr[t + 512];
    float s  = v0 + v1 + v2;
    float s2 = v0*v0 + v1*v1 + v2*v2;

    int lane = t & 31, w = t >> 5;
    #pragma unroll
    for (int o = 16; o; o >>= 1) {
        s  += __shfl_xor_sync(0xffffffffu, s,  o);
        s2 += __shfl_xor_sync(0xffffffffu, s2, o);
    }
    __shared__ float shs[8], shs2[8];
    if (lane == 0) { shs[w] = s; shs2[w] = s2; }
    __syncthreads();
    if (w == 0) {
        float a  = (lane < 8) ? shs[lane]  : 0.f;
        float a2 = (lane < 8) ? shs2[lane] : 0.f;
        #pragma unroll
        for (int o = 4; o; o >>= 1) {
            a  += __shfl_xor_sync(0xffffffffu, a,  o);
            a2 += __shfl_xor_sync(0xffffffffu, a2, o);
        }
        if (lane == 0) { shs[0] = a; shs2[0] = a2; }
    }
    __syncthreads();
    float mu  = shs[0] * (1.f / DIMC);
    float var = shs2[0] * (1.f / DIMC) - mu * mu;
    float r = rsqrtf(var + 1e-5f);

    float* o = g_xn + (size_t)row * DIMC;
    o[t]       = tfr((v0 - mu) * r * gamma[t]       + beta[t]);
    o[t + 256] = tfr((v1 - mu) * r * gamma[t + 256] + beta[t + 256]);
    o[t + 512] = tfr((v2 - mu) * r * gamma[t + 512] + beta[t + 512]);
}

// ---------------- depthwise 5x5 conv, smem-tiled ----------------
__global__ void __launch_bounds__(256) dw_kernel2(const float* __restrict__ w) {
    __shared__ float S[12][36][16];
    __shared__ float Ws[16][25];
    int c0 = blockIdx.x * 16;
    int y0 = blockIdx.y * 8;
    int b  = blockIdx.z;
    int tid = threadIdx.x;
    const float* xn_b = g_xn + ((size_t)b * NTOK + 1) * DIMC;

    for (int i = tid; i < 16 * 25; i += 256) {
        int c = i / 25, kk = i % 25;
        Ws[c][kk] = w[(c0 + c) * 25 + kk];
    }
    for (int i = tid; i < 12 * 36 * 16; i += 256) {
        int row = i / 576, rem = i % 576;
        int col = rem / 16, ch = rem % 16;
        int gy = y0 + row - 2, gx = col - 2;
        float v = 0.f;
        if (gy >= 0 && gy < FHW && gx >= 0 && gx < FHW)
            v = xn_b[(size_t)(gy * 32 + gx) * DIMC + c0 + ch];
        S[row][col][ch] = v;
    }
    __syncthreads();

    for (int k = 0; k < 16; k++) {
        int oi = k * 256 + tid;
        int oc = oi & 15;
        int ox = (oi >> 4) & 31;
        int oy = oi >> 9;
        float acc = 0.f;
        #pragma unroll
        for (int ky = 0; ky < 5; ky++)
            #pragma unroll
            for (int kx = 0; kx < 5; kx++)
                acc = fmaf(Ws[oc][ky * 5 + kx], S[oy + ky][ox + kx][oc], acc);
        g_dw[((size_t)b * SP + (y0 + oy) * 32 + ox) * DIMC + c0 + oc] = tfr(acc);
    }
}

// ---------------- tf32 MMA GEMM v3: 4-stage cp.async pipeline ---------------
#define ASTR 20
#define BSTR 136
#define STG  4

template<bool TB, bool HAS_BIAS>
__global__ void __launch_bounds__(256)
mma_gemm3(const float* __restrict__ A, const float* __restrict__ B,
          const float* __restrict__ bias, float* __restrict__ C,
          int M, int N, int K) {
    __shared__ __align__(16) float As[STG][128][ASTR];
    constexpr int BW = TB ? 128 * ASTR : 16 * BSTR;
    __shared__ __align__(16) float Bs[STG][BW];

    int tid = threadIdx.x;
    int lane = tid & 31, warp = tid >> 5;
    int wm = warp >> 2, wn = warp & 3;
    int g = lane >> 2, t4 = lane & 3;
    int bm = blockIdx.y * 128, bn = blockIdx.x * 128;

    int ar = tid >> 1, ak = (tid & 1) * 8;
    int bk = tid >> 4, n8 = (tid & 15) * 8;

    auto issue = [&](int st, int k0) {
        const float* ga = A + (size_t)(bm + ar) * K + k0 + ak;
        bool av = (bm + ar) < M;
        cp16(&As[st][ar][ak],     ga,     av);
        cp16(&As[st][ar][ak + 4], ga + 4, av);
        if (TB) {
            const float* gb = B + (size_t)(bn + ar) * K + k0 + ak;
            cp16(&Bs[st][ar * ASTR + ak],     gb,     true);
            cp16(&Bs[st][ar * ASTR + ak + 4], gb + 4, true);
        } else {
            const float* gb = B + (size_t)(k0 + bk) * N + bn + n8;
            cp16(&Bs[st][bk * BSTR + n8],     gb,     true);
            cp16(&Bs[st][bk * BSTR + n8 + 4], gb + 4, true);
        }
    };

    float acc[4][4][4];
    #pragma unroll
    for (int i = 0; i < 4; i++)
        #pragma unroll
        for (int j = 0; j < 4; j++)
            #pragma unroll
            for (int r = 0; r < 4; r++) acc[i][j][r] = 0.f;

    int NT = K >> 4;
    #pragma unroll
    for (int s = 0; s < STG - 1; s++) {
        if (s < NT) issue(s, s * 16);
        cp_commit();
    }

    for (int t = 0; t < NT; t++) {
        cp_waitg<STG - 2>();
        __syncthreads();
        int nt = t + STG - 1;
        if (nt < NT) issue(nt % STG, nt * 16);
        cp_commit();

        int cur = t % STG;
        #pragma unroll
        for (int kb = 0; kb < 16; kb += 8) {
            unsigned af[4][4], bf[4][2];
            #pragma unroll
            for (int mi = 0; mi < 4; mi++) {
                int m0 = wm * 64 + mi * 16 + g;
                af[mi][0] = __float_as_uint(As[cur][m0][kb + t4]);
                af[mi][1] = __float_as_uint(As[cur][m0 + 8][kb + t4]);
                af[mi][2] = __float_as_uint(As[cur][m0][kb + t4 + 4]);
                af[mi][3] = __float_as_uint(As[cur][m0 + 8][kb + t4 + 4]);
            }
            #pragma unroll
            for (int ni = 0; ni < 4; ni++) {
                int n0 = wn * 32 + ni * 8 + g;
                if (TB) {
                    bf[ni][0] = __float_as_uint(Bs[cur][n0 * ASTR + kb + t4]);
                    bf[ni][1] = __float_as_uint(Bs[cur][n0 * ASTR + kb + t4 + 4]);
                } else {
                    bf[ni][0] = __float_as_uint(Bs[cur][(kb + t4) * BSTR + n0]);
                    bf[ni][1] = __float_as_uint(Bs[cur][(kb + t4 + 4) * BSTR + n0]);
                }
            }
            #pragma unroll
            for (int mi = 0; mi < 4; mi++)
                #pragma unroll
                for (int ni = 0; ni < 4; ni++)
                    mma8(acc[mi][ni], af[mi], bf[ni]);
        }
    }

    #pragma unroll
    for (int mi = 0; mi < 4; mi++) {
        int row0 = bm + wm * 64 + mi * 16 + g;
        int row1 = row0 + 8;
        #pragma unroll
        for (int ni = 0; ni < 4; ni++) {
            int col = bn + wn * 32 + ni * 8 + 2 * t4;
            float b0 = 0.f, b1 = 0.f;
            if (HAS_BIAS) { b0 = bias[col]; b1 = bias[col + 1]; }
            if (row0 < M) {
                float2 v = make_float2(acc[mi][ni][0] + b0, acc[mi][ni][1] + b1);
                *(float2*)(C + (size_t)row0 * N + col) = v;
            }
            if (row1 < M) {
                float2 v = make_float2(acc[mi][ni][2] + b0, acc[mi][ni][3] + b1);
                *(float2*)(C + (size_t)row1 * N + col) = v;
            }
        }
    }
}

// ---------------- q assembly + rope + kv split ----------------
__global__ void assemble_kernel(const float* __restrict__ sinp,
                                const float* __restrict__ cosp) {
    int row = blockIdx.x;
    int b = row / NTOK, n = row % NTOK;
    const float* pwrow = (n > 0) ? (g_pw + ((size_t)b * SP + (n - 1)) * DIMC) : nullptr;
    const float* kvrow = g_kv + (size_t)row * NKV;
    const float* xnrow = g_xn + (size_t)row * DIMC;
    int pos = n - 1;

    for (int c = threadIdx.x; c < DIMC; c += 256) {
        float qv, kv_;
        float vv = kvrow[DIMC + c];
        kv_ = kvrow[c];
        if (n == 0) {
            qv = xnrow[c];
        } else {
            qv = pwrow[c];
            int d = c & 63;
            if (d < NROT) {
                float cs = cosp[pos * NROT + d];
                float sn = sinp[pos * NROT + d];
                float qpart = pwrow[c ^ 1];
                float kpart = kvrow[c ^ 1];
                float qrot = (d & 1) ? qpart : -qpart;
                float krot = (d & 1) ? kpart : -kpart;
                qv  = qv  * cs + qrot * sn;
                kv_ = kv_ * cs + krot * sn;
            }
        }
        g_q[(size_t)row * DIMC + c] = tfr(qv);
        g_k[(size_t)row * DIMC + c] = tfr(kv_);
        g_v[(size_t)row * DIMC + c] = tfr(vv);
    }
}

// ---------------- tensor-core flash attention, 2-stage cp.async K/V ---------
#define KTILE 64
#define KSTR  68
#define VSTR  72

__global__ void __launch_bounds__(256)
attn_mma_kernel() {
    __shared__ __align__(16) unsigned Ks[2][KTILE][KSTR];
    __shared__ __align__(16) unsigned Vs[2][KTILE][VSTR];

    int bh = blockIdx.x;
    int b = bh / HEADS, h = bh % HEADS;
    int qt0 = blockIdx.y * 128;
    int tid = threadIdx.x, lane = tid & 31, warp = tid >> 5;
    int g = lane >> 2, t4 = lane & 3;

    const float* qb = g_q + ((size_t)b * NTOK) * DIMC + h * DH;
    const float* kb = g_k + ((size_t)b * NTOK) * DIMC + h * DH;
    const float* vb = g_v + ((size_t)b * NTOK) * DIMC + h * DH;

    int r0 = qt0 + warp * 16 + g;
    int r1 = r0 + 8;

    auto issue_kv = [&](int st, int kt0) {
        #pragma unroll
        for (int lp = 0; lp < 4; lp++) {
            int pos = tid + lp * 256;
            int row = pos >> 4, c4 = pos & 15;
            int key = kt0 + row;
            bool v = key < NTOK;
            const float* kp = kb + (size_t)key * DIMC + c4 * 4;
            const float* vp = vb + (size_t)key * DIMC + c4 * 4;
            cp16(&Ks[st][row][c4 * 4], kp, v);
            cp16(&Vs[st][row][c4 * 4], vp, v);
        }
    };

    unsigned aq[8][4];
    #pragma unroll
    for (int kk = 0; kk < 8; kk++) {
        float x0 = 0.f, x1 = 0.f, x2 = 0.f, x3 = 0.f;
        if (r0 < NTOK) {
            x0 = qb[(size_t)r0 * DIMC + kk * 8 + t4];
            x2 = qb[(size_t)r0 * DIMC + kk * 8 + t4 + 4];
        }
        if (r1 < NTOK) {
            x1 = qb[(size_t)r1 * DIMC + kk * 8 + t4];
            x3 = qb[(size_t)r1 * DIMC + kk * 8 + t4 + 4];
        }
        aq[kk][0] = __float_as_uint(x0 * 0.125f);
        aq[kk][1] = __float_as_uint(x1 * 0.125f);
        aq[kk][2] = __float_as_uint(x2 * 0.125f);
        aq[kk][3] = __float_as_uint(x3 * 0.125f);
    }

    float o[8][4];
    #pragma unroll
    for (int i = 0; i < 8; i++)
        #pragma unroll
        for (int j = 0; j < 4; j++) o[i][j] = 0.f;
    float m0 = -1e30f, m1 = -1e30f, l0 = 0.f, l1 = 0.f;

    issue_kv(0, 0);
    cp_commit();

    const int NTILES = (NTOK + KTILE - 1) / KTILE;
    for (int it = 0; it < NTILES; it++) {
        __syncthreads();                 // writes into slot (it+1)&1 vs old reads
        if (it + 1 < NTILES) issue_kv((it + 1) & 1, (it + 1) * KTILE);
        cp_commit();
        cp_waitg<1>();
        __syncthreads();
        int st = it & 1;
        int kt0 = it * KTILE;

        float sc[8][4];
        #pragma unroll
        for (int i = 0; i < 8; i++)
            #pragma unroll
            for (int j = 0; j < 4; j++) sc[i][j] = 0.f;

        #pragma unroll
        for (int kk = 0; kk < 8; kk++) {
            #pragma unroll
            for (int ni = 0; ni < 8; ni++) {
                unsigned bf[2];
                bf[0] = Ks[st][ni * 8 + g][kk * 8 + t4];
                bf[1] = Ks[st][ni * 8 + g][kk * 8 + t4 + 4];
                mma8(sc[ni], aq[kk], bf);
            }
        }

        if (kt0 + KTILE > NTOK) {
            #pragma unroll
            for (int ni = 0; ni < 8; ni++) {
                int key = kt0 + ni * 8 + 2 * t4;
                if (key     >= NTOK) { sc[ni][0] = -1e30f; sc[ni][2] = -1e30f; }
                if (key + 1 >= NTOK) { sc[ni][1] = -1e30f; sc[ni][3] = -1e30f; }
            }
        }

        float mx0 = -1e30f, mx1 = -1e30f;
        #pragma unroll
        for (int ni = 0; ni < 8; ni++) {
            mx0 = fmaxf(mx0, fmaxf(sc[ni][0], sc[ni][1]));
            mx1 = fmaxf(mx1, fmaxf(sc[ni][2], sc[ni][3]));
        }
        mx0 = fmaxf(mx0, __shfl_xor_sync(0xffffffffu, mx0, 1));
        mx0 = fmaxf(mx0, __shfl_xor_sync(0xffffffffu, mx0, 2));
        mx1 = fmaxf(mx1, __shfl_xor_sync(0xffffffffu, mx1, 1));
        mx1 = fmaxf(mx1, __shfl_xor_sync(0xffffffffu, mx1, 2));
        float nm0 = fmaxf(m0, mx0), nm1 = fmaxf(m1, mx1);
        float cor0 = __expf(m0 - nm0), cor1 = __expf(m1 - nm1);
        m0 = nm0; m1 = nm1;

        float ps0 = 0.f, ps1 = 0.f;
        #pragma unroll
        for (int ni = 0; ni < 8; ni++) {
            sc[ni][0] = __expf(sc[ni][0] - nm0); ps0 += sc[ni][0];
            sc[ni][1] = __expf(sc[ni][1] - nm0); ps0 += sc[ni][1];
            sc[ni][2] = __expf(sc[ni][2] - nm1); ps1 += sc[ni][2];
            sc[ni][3] = __expf(sc[ni][3] - nm1); ps1 += sc[ni][3];
        }
        l0 = l0 * cor0 + ps0;
        l1 = l1 * cor1 + ps1;
        #pragma unroll
        for (int ni = 0; ni < 8; ni++) {
            o[ni][0] *= cor0; o[ni][1] *= cor0;
            o[ni][2] *= cor1; o[ni][3] *= cor1;
        }

        int srcA = (g << 2) | (t4 >> 1);
        int srcB = srcA + 2;
        bool hi = t4 & 1;
        #pragma unroll
        for (int kc = 0; kc < 8; kc++) {
            float v00 = __shfl_sync(0xffffffffu, sc[kc][0], srcA);
            float v01 = __shfl_sync(0xffffffffu, sc[kc][1], srcA);
            float v10 = __shfl_sync(0xffffffffu, sc[kc][2], srcA);
            float v11 = __shfl_sync(0xffffffffu, sc[kc][3], srcA);
            float w00 = __shfl_sync(0xffffffffu, sc[kc][0], srcB);
            float w01 = __shfl_sync(0xffffffffu, sc[kc][1], srcB);
            float w10 = __shfl_sync(0xffffffffu, sc[kc][2], srcB);
            float w11 = __shfl_sync(0xffffffffu, sc[kc][3], srcB);
            unsigned ap[4];
            ap[0] = f2tf(hi ? v01 : v00);
            ap[1] = f2tf(hi ? v11 : v10);
            ap[2] = f2tf(hi ? w01 : w00);
            ap[3] = f2tf(hi ? w11 : w10);
            #pragma unroll
            for (int ni = 0; ni < 8; ni++) {
                unsigned bf[2];
                bf[0] = Vs[st][kc * 8 + t4][ni * 8 + g];
                bf[1] = Vs[st][kc * 8 + t4 + 4][ni * 8 + g];
                mma8(o[ni], ap, bf);
            }
        }
    }

    l0 += __shfl_xor_sync(0xffffffffu, l0, 1);
    l0 += __shfl_xor_sync(0xffffffffu, l0, 2);
    l1 += __shfl_xor_sync(0xffffffffu, l1, 1);
    l1 += __shfl_xor_sync(0xffffffffu, l1, 2);
    float inv0 = 1.f / l0, inv1 = 1.f / l1;

    if (r0 < NTOK) {
        float* op = g_ao + ((size_t)b * NTOK + r0) * DIMC + h * DH;
        #pragma unroll
        for (int ni = 0; ni < 8; ni++)
            *(float2*)(op + ni * 8 + 2 * t4) =
                make_float2(tfr(o[ni][0] * inv0), tfr(o[ni][1] * inv0));
    }
    if (r1 < NTOK) {
        float* op = g_ao + ((size_t)b * NTOK + r1) * DIMC + h * DH;
        #pragma unroll
        for (int ni = 0; ni < 8; ni++)
            *(float2*)(op + ni * 8 + 2 * t4) =
                make_float2(tfr(o[ni][2] * inv1), tfr(o[ni][3] * inv1));
    }
}

// ---------------- launch ----------------
extern "C" void kernel_launch(void* const* d_in, const int* in_sizes, int n_in,
                              void* d_out, int out_size) {
    const float* x     = (const float*)d_in[0];
    const float* sinp  = (const float*)d_in[1];
    const float* cosp  = (const float*)d_in[2];
    const float* ln_g  = (const float*)d_in[3];
    const float* ln_b  = (const float*)d_in[4];
    const float* dw_w  = (const float*)d_in[5];
    const float* pw_w  = (const float*)d_in[6];
    const float* kv_w  = (const float*)d_in[7];
    const float* out_w = (const float*)d_in[8];
    const float* out_b = (const float*)d_in[9];
    float* out = (float*)d_out;

    float *p_dw, *p_pw, *p_xn, *p_kv, *p_ao, *p_pww, *p_kvw, *p_oww;
    cudaGetSymbolAddress((void**)&p_xn, g_xn);
    cudaGetSymbolAddress((void**)&p_dw, g_dw);
    cudaGetSymbolAddress((void**)&p_pw, g_pw);
    cudaGetSymbolAddress((void**)&p_kv, g_kv);
    cudaGetSymbolAddress((void**)&p_ao, g_ao);
    cudaGetSymbolAddress((void**)&p_pww, g_pww);
    cudaGetSymbolAddress((void**)&p_kvw, g_kvw);
    cudaGetSymbolAddress((void**)&p_oww, g_oww);

    round_w_kernel<<<(DIMC * NKV + 255) / 256, 256>>>(pw_w, kv_w, out_w);
    ln_kernel<<<BB * NTOK, 256>>>(x, ln_g, ln_b);
    dw_kernel2<<<dim3(DIMC / 16, 4, BB), 256>>>(dw_w);
    mma_gemm3<true, false><<<dim3(DIMC / 128, (BB * SP) / 128), 256>>>(
        p_dw, p_pww, nullptr, p_pw, BB * SP, DIMC, DIMC);
    mma_gemm3<false, false><<<dim3(NKV / 128, (BB * NTOK + 127) / 128), 256>>>(
        p_xn, p_kvw, nullptr, p_kv, BB * NTOK, NKV, DIMC);
    assemble_kernel<<<BB * NTOK, 256>>>(sinp, cosp);
    attn_mma_kernel<<<dim3(BB * HEADS, (NTOK + 127) / 128), 256>>>();
    mma_gemm3<false, true><<<dim3(DIMC / 128, (BB * NTOK + 127) / 128), 256>>>(
        p_ao, p_oww, out_b, out, BB * NTOK, DIMC, DIMC);
}

// round 7
// speedup vs baseline: 3.2907x; 1.0159x over previous
#include <cuda_runtime.h>
#include <math.h>

// ---------------- problem constants ----------------
#define BB    8
#define NTOK  1025
#define SP    1024
#define FHW   32
#define DIMC  768
#define NKV   1536
#define HEADS 12
#define DH    64
#define NROT  32

// ---------------- scratch ----------------
__device__ float g_xn[BB*NTOK*DIMC];
__device__ float g_dw[BB*SP*DIMC];
__device__ float g_pw[BB*SP*DIMC];
__device__ float g_kv[BB*NTOK*NKV];
__device__ float g_q [BB*NTOK*DIMC];
__device__ float g_k [BB*NTOK*DIMC];
__device__ float g_v [BB*NTOK*DIMC];
__device__ float g_ao[BB*NTOK*DIMC];
__device__ float g_pww[DIMC*DIMC];    // [N][K] (natural), tf32-rounded
__device__ float g_kvw[NKV*DIMC];     // transposed to [N][K], tf32-rounded
__device__ float g_oww[DIMC*DIMC];    // transposed to [N][K], tf32-rounded

// ---------------- tf32 / cp.async helpers ----------------
__device__ __forceinline__ unsigned f2tf(float f) {
    unsigned r;
    asm("cvt.rna.tf32.f32 %0, %1;" : "=r"(r) : "f"(f));
    return r;
}
__device__ __forceinline__ float tfr(float f) {
    return __uint_as_float(f2tf(f));
}
__device__ __forceinline__ void mma8(float* c, const unsigned* a, const unsigned* b) {
    asm volatile(
        "mma.sync.aligned.m16n8k8.row.col.f32.tf32.tf32.f32 "
        "{%0,%1,%2,%3}, {%4,%5,%6,%7}, {%8,%9}, {%0,%1,%2,%3};"
        : "+f"(c[0]), "+f"(c[1]), "+f"(c[2]), "+f"(c[3])
        : "r"(a[0]), "r"(a[1]), "r"(a[2]), "r"(a[3]), "r"(b[0]), "r"(b[1]));
}
__device__ __forceinline__ void cp16(void* dst, const void* src, bool valid) {
    unsigned d = (unsigned)__cvta_generic_to_shared(dst);
    int sz = valid ? 16 : 0;
    asm volatile("cp.async.ca.shared.global [%0], [%1], 16, %2;\n"
                 :: "r"(d), "l"(src), "r"(sz));
}
__device__ __forceinline__ void cp_commit() {
    asm volatile("cp.async.commit_group;\n");
}
template<int N>
__device__ __forceinline__ void cp_waitg() {
    asm volatile("cp.async.wait_group %0;\n" :: "n"(N));
}

// ---------------- weight prep: round / transpose+round ----------------
__global__ void round_pw_kernel(const float* __restrict__ pw) {
    int i = blockIdx.x * 256 + threadIdx.x;
    if (i < DIMC*DIMC) g_pww[i] = tfr(pw[i]);
}
// src: [K][N] row-major -> dst: [N][K] row-major, tf32-rounded
__global__ void transpose_w_kernel(const float* __restrict__ src,
                                   float* __restrict__ dst, int K, int N) {
    __shared__ float tile[32][33];
    int n0 = blockIdx.x * 32, k0 = blockIdx.y * 32;
    int tx = threadIdx.x, ty = threadIdx.y;
    #pragma unroll
    for (int dy = ty; dy < 32; dy += 8)
        tile[dy][tx] = tfr(src[(size_t)(k0 + dy) * N + n0 + tx]);
    __syncthreads();
    #pragma unroll
    for (int dy = ty; dy < 32; dy += 8)
        dst[(size_t)(n0 + dy) * K + k0 + tx] = tile[tx][dy];
}

// ---------------- layernorm ----------------
__global__ void ln_kernel(const float* __restrict__ x,
                          const float* __restrict__ gamma,
                          const float* __restrict__ beta) {
    int row = blockIdx.x;
    int t = threadIdx.x;
    const float* xr = x + (size_t)row * DIMC;

    float v0 = xr[t], v1 = xr[t + 256], v2 = xr[t + 512];
    float s  = v0 + v1 + v2;
    float s2 = v0*v0 + v1*v1 + v2*v2;

    int lane = t & 31, w = t >> 5;
    #pragma unroll
    for (int o = 16; o; o >>= 1) {
        s  += __shfl_xor_sync(0xffffffffu, s,  o);
        s2 += __shfl_xor_sync(0xffffffffu, s2, o);
    }
    __shared__ float shs[8], shs2[8];
    if (lane == 0) { shs[w] = s; shs2[w] = s2; }
    __syncthreads();
    if (w == 0) {
        float a  = (lane < 8) ? shs[lane]  : 0.f;
        float a2 = (lane < 8) ? shs2[lane] : 0.f;
        #pragma unroll
        for (int o = 4; o; o >>= 1) {
            a  += __shfl_xor_sync(0xffffffffu, a,  o);
            a2 += __shfl_xor_sync(0xffffffffu, a2, o);
        }
        if (lane == 0) { shs[0] = a; shs2[0] = a2; }
    }
    __syncthreads();
    float mu  = shs[0] * (1.f / DIMC);
    float var = shs2[0] * (1.f / DIMC) - mu * mu;
    float r = rsqrtf(var + 1e-5f);

    float* o = g_xn + (size_t)row * DIMC;
    o[t]       = tfr((v0 - mu) * r * gamma[t]       + beta[t]);
    o[t + 256] = tfr((v1 - mu) * r * gamma[t + 256] + beta[t + 256]);
    o[t + 512] = tfr((v2 - mu) * r * gamma[t + 512] + beta[t + 512]);
}

// ---------------- depthwise 5x5 conv, smem-tiled ----------------
__global__ void __launch_bounds__(256) dw_kernel2(const float* __restrict__ w) {
    __shared__ float S[12][36][16];
    __shared__ float Ws[16][25];
    int c0 = blockIdx.x * 16;
    int y0 = blockIdx.y * 8;
    int b  = blockIdx.z;
    int tid = threadIdx.x;
    const float* xn_b = g_xn + ((size_t)b * NTOK + 1) * DIMC;

    for (int i = tid; i < 16 * 25; i += 256) {
        int c = i / 25, kk = i % 25;
        Ws[c][kk] = w[(c0 + c) * 25 + kk];
    }
    for (int i = tid; i < 12 * 36 * 16; i += 256) {
        int row = i / 576, rem = i % 576;
        int col = rem / 16, ch = rem % 16;
        int gy = y0 + row - 2, gx = col - 2;
        float v = 0.f;
        if (gy >= 0 && gy < FHW && gx >= 0 && gx < FHW)
            v = xn_b[(size_t)(gy * 32 + gx) * DIMC + c0 + ch];
        S[row][col][ch] = v;
    }
    __syncthreads();

    for (int k = 0; k < 16; k++) {
        int oi = k * 256 + tid;
        int oc = oi & 15;
        int ox = (oi >> 4) & 31;
        int oy = oi >> 9;
        float acc = 0.f;
        #pragma unroll
        for (int ky = 0; ky < 5; ky++)
            #pragma unroll
            for (int kx = 0; kx < 5; kx++)
                acc = fmaf(Ws[oc][ky * 5 + kx], S[oy + ky][ox + kx][oc], acc);
        g_dw[((size_t)b * SP + (y0 + oy) * 32 + ox) * DIMC + c0 + oc] = tfr(acc);
    }
}

// ---------------- tf32 MMA GEMM v4: unified TB, LDS.64 frags, 2 CTAs/SM ----
// C[M,N] = A[M,K] @ B^T, B stored [N][K]. K%16==0, N%128==0.
// k-slot relabeling: within each k8 block, slot t4 -> k=2*t4, slot t4+4 -> k=2*t4+1.
#define WSTR 24    // row stride (words): 24*g%32 in {0,24,16,8} -> conflict-free LDS.64

template<bool HAS_BIAS>
__global__ void __launch_bounds__(256, 2)
mma_gemm4(const float* __restrict__ A, const float* __restrict__ B,
          const float* __restrict__ bias, float* __restrict__ C,
          int M, int N, int K) {
    __shared__ __align__(16) float As[2][128][WSTR];
    __shared__ __align__(16) float Bs[2][128][WSTR];

    int tid = threadIdx.x;
    int lane = tid & 31, warp = tid >> 5;
    int wm = warp >> 2, wn = warp & 3;
    int g = lane >> 2, t4 = lane & 3;
    int bm = blockIdx.y * 128, bn = blockIdx.x * 128;

    int ar = tid >> 1, ak = (tid & 1) * 8;

    auto issue = [&](int st, int k0) {
        const float* ga = A + (size_t)(bm + ar) * K + k0 + ak;
        bool av = (bm + ar) < M;
        cp16(&As[st][ar][ak],     ga,     av);
        cp16(&As[st][ar][ak + 4], ga + 4, av);
        const float* gb = B + (size_t)(bn + ar) * K + k0 + ak;
        cp16(&Bs[st][ar][ak],     gb,     true);
        cp16(&Bs[st][ar][ak + 4], gb + 4, true);
    };

    float acc[4][4][4];
    #pragma unroll
    for (int i = 0; i < 4; i++)
        #pragma unroll
        for (int j = 0; j < 4; j++)
            #pragma unroll
            for (int r = 0; r < 4; r++) acc[i][j][r] = 0.f;

    issue(0, 0);
    cp_commit();

    int NT = K >> 4;
    for (int t = 0; t < NT; t++) {
        if (t > 0) __syncthreads();
        if (t + 1 < NT) issue((t + 1) & 1, (t + 1) * 16);
        cp_commit();
        cp_waitg<1>();
        __syncthreads();
        int cur = t & 1;

        #pragma unroll
        for (int kb = 0; kb < 16; kb += 8) {
            int kc = kb + 2 * t4;
            unsigned af[4][4], bf[4][2];
            #pragma unroll
            for (int mi = 0; mi < 4; mi++) {
                int m0 = wm * 64 + mi * 16 + g;
                float2 a02 = *(const float2*)&As[cur][m0][kc];
                float2 a13 = *(const float2*)&As[cur][m0 + 8][kc];
                af[mi][0] = __float_as_uint(a02.x);
                af[mi][1] = __float_as_uint(a13.x);
                af[mi][2] = __float_as_uint(a02.y);
                af[mi][3] = __float_as_uint(a13.y);
            }
            #pragma unroll
            for (int ni = 0; ni < 4; ni++) {
                int n0 = wn * 32 + ni * 8 + g;
                float2 b01 = *(const float2*)&Bs[cur][n0][kc];
                bf[ni][0] = __float_as_uint(b01.x);
                bf[ni][1] = __float_as_uint(b01.y);
            }
            #pragma unroll
            for (int mi = 0; mi < 4; mi++)
                #pragma unroll
                for (int ni = 0; ni < 4; ni++)
                    mma8(acc[mi][ni], af[mi], bf[ni]);
        }
    }

    #pragma unroll
    for (int mi = 0; mi < 4; mi++) {
        int row0 = bm + wm * 64 + mi * 16 + g;
        int row1 = row0 + 8;
        #pragma unroll
        for (int ni = 0; ni < 4; ni++) {
            int col = bn + wn * 32 + ni * 8 + 2 * t4;
            float b0 = 0.f, b1 = 0.f;
            if (HAS_BIAS) { b0 = bias[col]; b1 = bias[col + 1]; }
            if (row0 < M) {
                float2 v = make_float2(acc[mi][ni][0] + b0, acc[mi][ni][1] + b1);
                *(float2*)(C + (size_t)row0 * N + col) = v;
            }
            if (row1 < M) {
                float2 v = make_float2(acc[mi][ni][2] + b0, acc[mi][ni][3] + b1);
                *(float2*)(C + (size_t)row1 * N + col) = v;
            }
        }
    }
}

// ---------------- q assembly + rope + kv split ----------------
__global__ void assemble_kernel(const float* __restrict__ sinp,
                                const float* __restrict__ cosp) {
    int row = blockIdx.x;
    int b = row / NTOK, n = row % NTOK;
    const float* pwrow = (n > 0) ? (g_pw + ((size_t)b * SP + (n - 1)) * DIMC) : nullptr;
    const float* kvrow = g_kv + (size_t)row * NKV;
    const float* xnrow = g_xn + (size_t)row * DIMC;
    int pos = n - 1;

    for (int c = threadIdx.x; c < DIMC; c += 256) {
        float qv, kv_;
        float vv = kvrow[DIMC + c];
        kv_ = kvrow[c];
        if (n == 0) {
            qv = xnrow[c];
        } else {
            qv = pwrow[c];
            int d = c & 63;
            if (d < NROT) {
                float cs = cosp[pos * NROT + d];
                float sn = sinp[pos * NROT + d];
                float qpart = pwrow[c ^ 1];
                float kpart = kvrow[c ^ 1];
                float qrot = (d & 1) ? qpart : -qpart;
                float krot = (d & 1) ? kpart : -kpart;
                qv  = qv  * cs + qrot * sn;
                kv_ = kv_ * cs + krot * sn;
            }
        }
        g_q[(size_t)row * DIMC + c] = tfr(qv);
        g_k[(size_t)row * DIMC + c] = tfr(kv_);
        g_v[(size_t)row * DIMC + c] = tfr(vv);
    }
}

// ---------------- tensor-core flash attention, 2-stage cp.async K/V ---------
#define KTILE 64
#define KSTR  68
#define VSTR  72

__global__ void __launch_bounds__(256)
attn_mma_kernel() {
    __shared__ __align__(16) unsigned Ks[2][KTILE][KSTR];
    __shared__ __align__(16) unsigned Vs[2][KTILE][VSTR];

    int bh = blockIdx.x;
    int b = bh / HEADS, h = bh % HEADS;
    int qt0 = blockIdx.y * 128;
    int tid = threadIdx.x, lane = tid & 31, warp = tid >> 5;
    int g = lane >> 2, t4 = lane & 3;

    const float* qb = g_q + ((size_t)b * NTOK) * DIMC + h * DH;
    const float* kb = g_k + ((size_t)b * NTOK) * DIMC + h * DH;
    const float* vb = g_v + ((size_t)b * NTOK) * DIMC + h * DH;

    int r0 = qt0 + warp * 16 + g;
    int r1 = r0 + 8;

    auto issue_kv = [&](int st, int kt0) {
        #pragma unroll
        for (int lp = 0; lp < 4; lp++) {
            int pos = tid + lp * 256;
            int row = pos >> 4, c4 = pos & 15;
            int key = kt0 + row;
            bool v = key < NTOK;
            const float* kp = kb + (size_t)key * DIMC + c4 * 4;
            const float* vp = vb + (size_t)key * DIMC + c4 * 4;
            cp16(&Ks[st][row][c4 * 4], kp, v);
            cp16(&Vs[st][row][c4 * 4], vp, v);
        }
    };

    unsigned aq[8][4];
    #pragma unroll
    for (int kk = 0; kk < 8; kk++) {
        float x0 = 0.f, x1 = 0.f, x2 = 0.f, x3 = 0.f;
        if (r0 < NTOK) {
            x0 = qb[(size_t)r0 * DIMC + kk * 8 + t4];
            x2 = qb[(size_t)r0 * DIMC + kk * 8 + t4 + 4];
        }
        if (r1 < NTOK) {
            x1 = qb[(size_t)r1 * DIMC + kk * 8 + t4];
            x3 = qb[(size_t)r1 * DIMC + kk * 8 + t4 + 4];
        }
        aq[kk][0] = __float_as_uint(x0 * 0.125f);
        aq[kk][1] = __float_as_uint(x1 * 0.125f);
        aq[kk][2] = __float_as_uint(x2 * 0.125f);
        aq[kk][3] = __float_as_uint(x3 * 0.125f);
    }

    float o[8][4];
    #pragma unroll
    for (int i = 0; i < 8; i++)
        #pragma unroll
        for (int j = 0; j < 4; j++) o[i][j] = 0.f;
    float m0 = -1e30f, m1 = -1e30f, l0 = 0.f, l1 = 0.f;

    issue_kv(0, 0);
    cp_commit();

    const int NTILES = (NTOK + KTILE - 1) / KTILE;
    for (int it = 0; it < NTILES; it++) {
        __syncthreads();
        if (it + 1 < NTILES) issue_kv((it + 1) & 1, (it + 1) * KTILE);
        cp_commit();
        cp_waitg<1>();
        __syncthreads();
        int st = it & 1;
        int kt0 = it * KTILE;

        float sc[8][4];
        #pragma unroll
        for (int i = 0; i < 8; i++)
            #pragma unroll
            for (int j = 0; j < 4; j++) sc[i][j] = 0.f;

        #pragma unroll
        for (int kk = 0; kk < 8; kk++) {
            #pragma unroll
            for (int ni = 0; ni < 8; ni++) {
                unsigned bf[2];
                bf[0] = Ks[st][ni * 8 + g][kk * 8 + t4];
                bf[1] = Ks[st][ni * 8 + g][kk * 8 + t4 + 4];
                mma8(sc[ni], aq[kk], bf);
            }
        }

        if (kt0 + KTILE > NTOK) {
            #pragma unroll
            for (int ni = 0; ni < 8; ni++) {
                int key = kt0 + ni * 8 + 2 * t4;
                if (key     >= NTOK) { sc[ni][0] = -1e30f; sc[ni][2] = -1e30f; }
                if (key + 1 >= NTOK) { sc[ni][1] = -1e30f; sc[ni][3] = -1e30f; }
            }
        }

        float mx0 = -1e30f, mx1 = -1e30f;
        #pragma unroll
        for (int ni = 0; ni < 8; ni++) {
            mx0 = fmaxf(mx0, fmaxf(sc[ni][0], sc[ni][1]));
            mx1 = fmaxf(mx1, fmaxf(sc[ni][2], sc[ni][3]));
        }
        mx0 = fmaxf(mx0, __shfl_xor_sync(0xffffffffu, mx0, 1));
        mx0 = fmaxf(mx0, __shfl_xor_sync(0xffffffffu, mx0, 2));
        mx1 = fmaxf(mx1, __shfl_xor_sync(0xffffffffu, mx1, 1));
        mx1 = fmaxf(mx1, __shfl_xor_sync(0xffffffffu, mx1, 2));
        float nm0 = fmaxf(m0, mx0), nm1 = fmaxf(m1, mx1);
        float cor0 = __expf(m0 - nm0), cor1 = __expf(m1 - nm1);
        m0 = nm0; m1 = nm1;

        float ps0 = 0.f, ps1 = 0.f;
        #pragma unroll
        for (int ni = 0; ni < 8; ni++) {
            sc[ni][0] = __expf(sc[ni][0] - nm0); ps0 += sc[ni][0];
            sc[ni][1] = __expf(sc[ni][1] - nm0); ps0 += sc[ni][1];
            sc[ni][2] = __expf(sc[ni][2] - nm1); ps1 += sc[ni][2];
            sc[ni][3] = __expf(sc[ni][3] - nm1); ps1 += sc[ni][3];
        }
        l0 = l0 * cor0 + ps0;
        l1 = l1 * cor1 + ps1;
        #pragma unroll
        for (int ni = 0; ni < 8; ni++) {
            o[ni][0] *= cor0; o[ni][1] *= cor0;
            o[ni][2] *= cor1; o[ni][3] *= cor1;
        }

        int srcA = (g << 2) | (t4 >> 1);
        int srcB = srcA + 2;
        bool hi = t4 & 1;
        #pragma unroll
        for (int kc = 0; kc < 8; kc++) {
            float v00 = __shfl_sync(0xffffffffu, sc[kc][0], srcA);
            float v01 = __shfl_sync(0xffffffffu, sc[kc][1], srcA);
            float v10 = __shfl_sync(0xffffffffu, sc[kc][2], srcA);
            float v11 = __shfl_sync(0xffffffffu, sc[kc][3], srcA);
            float w00 = __shfl_sync(0xffffffffu, sc[kc][0], srcB);
            float w01 = __shfl_sync(0xffffffffu, sc[kc][1], srcB);
            float w10 = __shfl_sync(0xffffffffu, sc[kc][2], srcB);
            float w11 = __shfl_sync(0xffffffffu, sc[kc][3], srcB);
            unsigned ap[4];
            ap[0] = f2tf(hi ? v01 : v00);
            ap[1] = f2tf(hi ? v11 : v10);
            ap[2] = f2tf(hi ? w01 : w00);
            ap[3] = f2tf(hi ? w11 : w10);
            #pragma unroll
            for (int ni = 0; ni < 8; ni++) {
                unsigned bf[2];
                bf[0] = Vs[st][kc * 8 + t4][ni * 8 + g];
                bf[1] = Vs[st][kc * 8 + t4 + 4][ni * 8 + g];
                mma8(o[ni], ap, bf);
            }
        }
    }

    l0 += __shfl_xor_sync(0xffffffffu, l0, 1);
    l0 += __shfl_xor_sync(0xffffffffu, l0, 2);
    l1 += __shfl_xor_sync(0xffffffffu, l1, 1);
    l1 += __shfl_xor_sync(0xffffffffu, l1, 2);
    float inv0 = 1.f / l0, inv1 = 1.f / l1;

    if (r0 < NTOK) {
        float* op = g_ao + ((size_t)b * NTOK + r0) * DIMC + h * DH;
        #pragma unroll
        for (int ni = 0; ni < 8; ni++)
            *(float2*)(op + ni * 8 + 2 * t4) =
                make_float2(tfr(o[ni][0] * inv0), tfr(o[ni][1] * inv0));
    }
    if (r1 < NTOK) {
        float* op = g_ao + ((size_t)b * NTOK + r1) * DIMC + h * DH;
        #pragma unroll
        for (int ni = 0; ni < 8; ni++)
            *(float2*)(op + ni * 8 + 2 * t4) =
                make_float2(tfr(o[ni][2] * inv1), tfr(o[ni][3] * inv1));
    }
}

// ---------------- launch ----------------
extern "C" void kernel_launch(void* const* d_in, const int* in_sizes, int n_in,
                              void* d_out, int out_size) {
    const float* x     = (const float*)d_in[0];
    const float* sinp  = (const float*)d_in[1];
    const float* cosp  = (const float*)d_in[2];
    const float* ln_g  = (const float*)d_in[3];
    const float* ln_b  = (const float*)d_in[4];
    const float* dw_w  = (const float*)d_in[5];
    const float* pw_w  = (const float*)d_in[6];
    const float* kv_w  = (const float*)d_in[7];
    const float* out_w = (const float*)d_in[8];
    const float* out_b = (const float*)d_in[9];
    float* out = (float*)d_out;

    float *p_dw, *p_pw, *p_xn, *p_kv, *p_ao, *p_pww, *p_kvw, *p_oww;
    cudaGetSymbolAddress((void**)&p_xn, g_xn);
    cudaGetSymbolAddress((void**)&p_dw, g_dw);
    cudaGetSymbolAddress((void**)&p_pw, g_pw);
    cudaGetSymbolAddress((void**)&p_kv, g_kv);
    cudaGetSymbolAddress((void**)&p_ao, g_ao);
    cudaGetSymbolAddress((void**)&p_pww, g_pww);
    cudaGetSymbolAddress((void**)&p_kvw, g_kvw);
    cudaGetSymbolAddress((void**)&p_oww, g_oww);

    // weight prep: pw round; kv/out transpose+round to [N][K]
    round_pw_kernel<<<(DIMC * DIMC + 255) / 256, 256>>>(pw_w);
    transpose_w_kernel<<<dim3(NKV / 32, DIMC / 32), dim3(32, 8)>>>(kv_w, p_kvw, DIMC, NKV);
    transpose_w_kernel<<<dim3(DIMC / 32, DIMC / 32), dim3(32, 8)>>>(out_w, p_oww, DIMC, DIMC);

    ln_kernel<<<BB * NTOK, 256>>>(x, ln_g, ln_b);
    dw_kernel2<<<dim3(DIMC / 16, 4, BB), 256>>>(dw_w);
    // pointwise conv: g_pw = g_dw @ pw_w^T    (M=8192, N=768, K=768)
    mma_gemm4<false><<<dim3(DIMC / 128, (BB * SP) / 128), 256>>>(
        p_dw, p_pww, nullptr, p_pw, BB * SP, DIMC, DIMC);
    // kv gemm: g_kv = g_xn @ kv_w             (M=8200, N=1536, K=768)
    mma_gemm4<false><<<dim3(NKV / 128, (BB * NTOK + 127) / 128), 256>>>(
        p_xn, p_kvw, nullptr, p_kv, BB * NTOK, NKV, DIMC);
    assemble_kernel<<<BB * NTOK, 256>>>(sinp, cosp);
    attn_mma_kernel<<<dim3(BB * HEADS, (NTOK + 127) / 128), 256>>>();
    // output projection + bias                (M=8200, N=768, K=768)
    mma_gemm4<true><<<dim3(DIMC / 128, (BB * NTOK + 127) / 128), 256>>>(
        p_ao, p_oww, out_b, out, BB * NTOK, DIMC, DIMC);
}

// round 8
// speedup vs baseline: 3.3087x; 1.0055x over previous
#include <cuda_runtime.h>
#include <math.h>

// ---------------- problem constants ----------------
#define BB    8
#define NTOK  1025
#define SP    1024
#define FHW   32
#define DIMC  768
#define NKV   1536
#define HEADS 12
#define DH    64
#define NROT  32

// ---------------- scratch ----------------
__device__ float g_xn[BB*NTOK*DIMC];
__device__ float g_dw[BB*SP*DIMC];
__device__ float g_pw[BB*SP*DIMC];
__device__ float g_kv[BB*NTOK*NKV];
__device__ float g_q [BB*NTOK*DIMC];
__device__ float g_k [BB*NTOK*DIMC];
__device__ float g_v [BB*NTOK*DIMC];
__device__ float g_ao[BB*NTOK*DIMC];
__device__ float g_pww[DIMC*DIMC];    // [N][K] (natural), tf32-rounded
__device__ float g_kvw[NKV*DIMC];     // transposed to [N][K], tf32-rounded
__device__ float g_oww[DIMC*DIMC];    // transposed to [N][K], tf32-rounded

// ---------------- tf32 / cp.async helpers ----------------
__device__ __forceinline__ unsigned f2tf(float f) {
    unsigned r;
    asm("cvt.rna.tf32.f32 %0, %1;" : "=r"(r) : "f"(f));
    return r;
}
__device__ __forceinline__ float tfr(float f) {
    return __uint_as_float(f2tf(f));
}
__device__ __forceinline__ void mma8(float* c, const unsigned* a, const unsigned* b) {
    asm volatile(
        "mma.sync.aligned.m16n8k8.row.col.f32.tf32.tf32.f32 "
        "{%0,%1,%2,%3}, {%4,%5,%6,%7}, {%8,%9}, {%0,%1,%2,%3};"
        : "+f"(c[0]), "+f"(c[1]), "+f"(c[2]), "+f"(c[3])
        : "r"(a[0]), "r"(a[1]), "r"(a[2]), "r"(a[3]), "r"(b[0]), "r"(b[1]));
}
__device__ __forceinline__ void cp16(void* dst, const void* src, bool valid) {
    unsigned d = (unsigned)__cvta_generic_to_shared(dst);
    int sz = valid ? 16 : 0;
    asm volatile("cp.async.ca.shared.global [%0], [%1], 16, %2;\n"
                 :: "r"(d), "l"(src), "r"(sz));
}
__device__ __forceinline__ void cp_commit() {
    asm volatile("cp.async.commit_group;\n");
}
template<int N>
__device__ __forceinline__ void cp_waitg() {
    asm volatile("cp.async.wait_group %0;\n" :: "n"(N));
}

// ---------------- weight prep: round / transpose+round ----------------
__global__ void round_pw_kernel(const float* __restrict__ pw) {
    int i = blockIdx.x * 256 + threadIdx.x;
    if (i < DIMC*DIMC) g_pww[i] = tfr(pw[i]);
}
// src: [K][N] row-major -> dst: [N][K] row-major, tf32-rounded
__global__ void transpose_w_kernel(const float* __restrict__ src,
                                   float* __restrict__ dst, int K, int N) {
    __shared__ float tile[32][33];
    int n0 = blockIdx.x * 32, k0 = blockIdx.y * 32;
    int tx = threadIdx.x, ty = threadIdx.y;
    #pragma unroll
    for (int dy = ty; dy < 32; dy += 8)
        tile[dy][tx] = tfr(src[(size_t)(k0 + dy) * N + n0 + tx]);
    __syncthreads();
    #pragma unroll
    for (int dy = ty; dy < 32; dy += 8)
        dst[(size_t)(n0 + dy) * K + k0 + tx] = tile[tx][dy];
}

// ---------------- layernorm ----------------
__global__ void ln_kernel(const float* __restrict__ x,
                          const float* __restrict__ gamma,
                          const float* __restrict__ beta) {
    int row = blockIdx.x;
    int t = threadIdx.x;
    const float* xr = x + (size_t)row * DIMC;

    float v0 = xr[t], v1 = xr[t + 256], v2 = xr[t + 512];
    float s  = v0 + v1 + v2;
    float s2 = v0*v0 + v1*v1 + v2*v2;

    int lane = t & 31, w = t >> 5;
    #pragma unroll
    for (int o = 16; o; o >>= 1) {
        s  += __shfl_xor_sync(0xffffffffu, s,  o);
        s2 += __shfl_xor_sync(0xffffffffu, s2, o);
    }
    __shared__ float shs[8], shs2[8];
    if (lane == 0) { shs[w] = s; shs2[w] = s2; }
    __syncthreads();
    if (w == 0) {
        float a  = (lane < 8) ? shs[lane]  : 0.f;
        float a2 = (lane < 8) ? shs2[lane] : 0.f;
        #pragma unroll
        for (int o = 4; o; o >>= 1) {
            a  += __shfl_xor_sync(0xffffffffu, a,  o);
            a2 += __shfl_xor_sync(0xffffffffu, a2, o);
        }
        if (lane == 0) { shs[0] = a; shs2[0] = a2; }
    }
    __syncthreads();
    float mu  = shs[0] * (1.f / DIMC);
    float var = shs2[0] * (1.f / DIMC) - mu * mu;
    float r = rsqrtf(var + 1e-5f);

    float* o = g_xn + (size_t)row * DIMC;
    o[t]       = tfr((v0 - mu) * r * gamma[t]       + beta[t]);
    o[t + 256] = tfr((v1 - mu) * r * gamma[t + 256] + beta[t + 256]);
    o[t + 512] = tfr((v2 - mu) * r * gamma[t + 512] + beta[t + 512]);
}

// ---------------- depthwise 5x5 conv, smem-tiled ----------------
__global__ void __launch_bounds__(256) dw_kernel2(const float* __restrict__ w) {
    __shared__ float S[12][36][16];
    __shared__ float Ws[16][25];
    int c0 = blockIdx.x * 16;
    int y0 = blockIdx.y * 8;
    int b  = blockIdx.z;
    int tid = threadIdx.x;
    const float* xn_b = g_xn + ((size_t)b * NTOK + 1) * DIMC;

    for (int i = tid; i < 16 * 25; i += 256) {
        int c = i / 25, kk = i % 25;
        Ws[c][kk] = w[(c0 + c) * 25 + kk];
    }
    for (int i = tid; i < 12 * 36 * 16; i += 256) {
        int row = i / 576, rem = i % 576;
        int col = rem / 16, ch = rem % 16;
        int gy = y0 + row - 2, gx = col - 2;
        float v = 0.f;
        if (gy >= 0 && gy < FHW && gx >= 0 && gx < FHW)
            v = xn_b[(size_t)(gy * 32 + gx) * DIMC + c0 + ch];
        S[row][col][ch] = v;
    }
    __syncthreads();

    for (int k = 0; k < 16; k++) {
        int oi = k * 256 + tid;
        int oc = oi & 15;
        int ox = (oi >> 4) & 31;
        int oy = oi >> 9;
        float acc = 0.f;
        #pragma unroll
        for (int ky = 0; ky < 5; ky++)
            #pragma unroll
            for (int kx = 0; kx < 5; kx++)
                acc = fmaf(Ws[oc][ky * 5 + kx], S[oy + ky][ox + kx][oc], acc);
        g_dw[((size_t)b * SP + (y0 + oy) * 32 + ox) * DIMC + c0 + oc] = tfr(acc);
    }
}

// ---------------- tf32 MMA GEMM v4: unified TB, LDS.64 frags, 2 CTAs/SM ----
// C[M,N] = A[M,K] @ B^T, B stored [N][K]. K%16==0, N%128==0.
// k-slot relabeling: within each k8 block, slot t4 -> k=2*t4, slot t4+4 -> k=2*t4+1.
#define WSTR 24    // row stride (words): 24*g%32 in {0,24,16,8} -> conflict-free LDS.64

template<bool HAS_BIAS>
__global__ void __launch_bounds__(256, 2)
mma_gemm4(const float* __restrict__ A, const float* __restrict__ B,
          const float* __restrict__ bias, float* __restrict__ C,
          int M, int N, int K) {
    __shared__ __align__(16) float As[2][128][WSTR];
    __shared__ __align__(16) float Bs[2][128][WSTR];

    int tid = threadIdx.x;
    int lane = tid & 31, warp = tid >> 5;
    int wm = warp >> 2, wn = warp & 3;
    int g = lane >> 2, t4 = lane & 3;
    int bm = blockIdx.y * 128, bn = blockIdx.x * 128;

    int ar = tid >> 1, ak = (tid & 1) * 8;

    auto issue = [&](int st, int k0) {
        const float* ga = A + (size_t)(bm + ar) * K + k0 + ak;
        bool av = (bm + ar) < M;
        cp16(&As[st][ar][ak],     ga,     av);
        cp16(&As[st][ar][ak + 4], ga + 4, av);
        const float* gb = B + (size_t)(bn + ar) * K + k0 + ak;
        cp16(&Bs[st][ar][ak],     gb,     true);
        cp16(&Bs[st][ar][ak + 4], gb + 4, true);
    };

    float acc[4][4][4];
    #pragma unroll
    for (int i = 0; i < 4; i++)
        #pragma unroll
        for (int j = 0; j < 4; j++)
            #pragma unroll
            for (int r = 0; r < 4; r++) acc[i][j][r] = 0.f;

    issue(0, 0);
    cp_commit();

    int NT = K >> 4;
    for (int t = 0; t < NT; t++) {
        if (t > 0) __syncthreads();
        if (t + 1 < NT) issue((t + 1) & 1, (t + 1) * 16);
        cp_commit();
        cp_waitg<1>();
        __syncthreads();
        int cur = t & 1;

        #pragma unroll
        for (int kb = 0; kb < 16; kb += 8) {
            int kc = kb + 2 * t4;
            unsigned af[4][4], bf[4][2];
            #pragma unroll
            for (int mi = 0; mi < 4; mi++) {
                int m0 = wm * 64 + mi * 16 + g;
                float2 a02 = *(const float2*)&As[cur][m0][kc];
                float2 a13 = *(const float2*)&As[cur][m0 + 8][kc];
                af[mi][0] = __float_as_uint(a02.x);
                af[mi][1] = __float_as_uint(a13.x);
                af[mi][2] = __float_as_uint(a02.y);
                af[mi][3] = __float_as_uint(a13.y);
            }
            #pragma unroll
            for (int ni = 0; ni < 4; ni++) {
                int n0 = wn * 32 + ni * 8 + g;
                float2 b01 = *(const float2*)&Bs[cur][n0][kc];
                bf[ni][0] = __float_as_uint(b01.x);
                bf[ni][1] = __float_as_uint(b01.y);
            }
            #pragma unroll
            for (int mi = 0; mi < 4; mi++)
                #pragma unroll
                for (int ni = 0; ni < 4; ni++)
                    mma8(acc[mi][ni], af[mi], bf[ni]);
        }
    }

    #pragma unroll
    for (int mi = 0; mi < 4; mi++) {
        int row0 = bm + wm * 64 + mi * 16 + g;
        int row1 = row0 + 8;
        #pragma unroll
        for (int ni = 0; ni < 4; ni++) {
            int col = bn + wn * 32 + ni * 8 + 2 * t4;
            float b0 = 0.f, b1 = 0.f;
            if (HAS_BIAS) { b0 = bias[col]; b1 = bias[col + 1]; }
            if (row0 < M) {
                float2 v = make_float2(acc[mi][ni][0] + b0, acc[mi][ni][1] + b1);
                *(float2*)(C + (size_t)row0 * N + col) = v;
            }
            if (row1 < M) {
                float2 v = make_float2(acc[mi][ni][2] + b0, acc[mi][ni][3] + b1);
                *(float2*)(C + (size_t)row1 * N + col) = v;
            }
        }
    }
}

// ---------------- q assembly + rope + kv split ----------------
__global__ void assemble_kernel(const float* __restrict__ sinp,
                                const float* __restrict__ cosp) {
    int row = blockIdx.x;
    int b = row / NTOK, n = row % NTOK;
    const float* pwrow = (n > 0) ? (g_pw + ((size_t)b * SP + (n - 1)) * DIMC) : nullptr;
    const float* kvrow = g_kv + (size_t)row * NKV;
    const float* xnrow = g_xn + (size_t)row * DIMC;
    int pos = n - 1;

    for (int c = threadIdx.x; c < DIMC; c += 256) {
        float qv, kv_;
        float vv = kvrow[DIMC + c];
        kv_ = kvrow[c];
        if (n == 0) {
            qv = xnrow[c];
        } else {
            qv = pwrow[c];
            int d = c & 63;
            if (d < NROT) {
                float cs = cosp[pos * NROT + d];
                float sn = sinp[pos * NROT + d];
                float qpart = pwrow[c ^ 1];
                float kpart = kvrow[c ^ 1];
                float qrot = (d & 1) ? qpart : -qpart;
                float krot = (d & 1) ? kpart : -kpart;
                qv  = qv  * cs + qrot * sn;
                kv_ = kv_ * cs + krot * sn;
            }
        }
        g_q[(size_t)row * DIMC + c] = tfr(qv);
        g_k[(size_t)row * DIMC + c] = tfr(kv_);
        g_v[(size_t)row * DIMC + c] = tfr(vv);
    }
}

// ---------------- tensor-core flash attention, 2-stage cp.async K/V ---------
#define KTILE 64
#define KSTR  68
#define VSTR  72

__global__ void __launch_bounds__(256)
attn_mma_kernel() {
    __shared__ __align__(16) unsigned Ks[2][KTILE][KSTR];
    __shared__ __align__(16) unsigned Vs[2][KTILE][VSTR];

    int bh = blockIdx.x;
    int b = bh / HEADS, h = bh % HEADS;
    int qt0 = blockIdx.y * 128;
    int tid = threadIdx.x, lane = tid & 31, warp = tid >> 5;
    int g = lane >> 2, t4 = lane & 3;

    const float* qb = g_q + ((size_t)b * NTOK) * DIMC + h * DH;
    const float* kb = g_k + ((size_t)b * NTOK) * DIMC + h * DH;
    const float* vb = g_v + ((size_t)b * NTOK) * DIMC + h * DH;

    int r0 = qt0 + warp * 16 + g;
    int r1 = r0 + 8;

    auto issue_kv = [&](int st, int kt0) {
        #pragma unroll
        for (int lp = 0; lp < 4; lp++) {
            int pos = tid + lp * 256;
            int row = pos >> 4, c4 = pos & 15;
            int key = kt0 + row;
            bool v = key < NTOK;
            const float* kp = kb + (size_t)key * DIMC + c4 * 4;
            const float* vp = vb + (size_t)key * DIMC + c4 * 4;
            cp16(&Ks[st][row][c4 * 4], kp, v);
            cp16(&Vs[st][row][c4 * 4], vp, v);
        }
    };

    unsigned aq[8][4];
    #pragma unroll
    for (int kk = 0; kk < 8; kk++) {
        float x0 = 0.f, x1 = 0.f, x2 = 0.f, x3 = 0.f;
        if (r0 < NTOK) {
            x0 = qb[(size_t)r0 * DIMC + kk * 8 + t4];
            x2 = qb[(size_t)r0 * DIMC + kk * 8 + t4 + 4];
        }
        if (r1 < NTOK) {
            x1 = qb[(size_t)r1 * DIMC + kk * 8 + t4];
            x3 = qb[(size_t)r1 * DIMC + kk * 8 + t4 + 4];
        }
        aq[kk][0] = __float_as_uint(x0 * 0.125f);
        aq[kk][1] = __float_as_uint(x1 * 0.125f);
        aq[kk][2] = __float_as_uint(x2 * 0.125f);
        aq[kk][3] = __float_as_uint(x3 * 0.125f);
    }

    float o[8][4];
    #pragma unroll
    for (int i = 0; i < 8; i++)
        #pragma unroll
        for (int j = 0; j < 4; j++) o[i][j] = 0.f;
    float m0 = -1e30f, m1 = -1e30f, l0 = 0.f, l1 = 0.f;

    issue_kv(0, 0);
    cp_commit();

    const int NTILES = (NTOK + KTILE - 1) / KTILE;
    for (int it = 0; it < NTILES; it++) {
        __syncthreads();
        if (it + 1 < NTILES) issue_kv((it + 1) & 1, (it + 1) * KTILE);
        cp_commit();
        cp_waitg<1>();
        __syncthreads();
        int st = it & 1;
        int kt0 = it * KTILE;

        float sc[8][4];
        #pragma unroll
        for (int i = 0; i < 8; i++)
            #pragma unroll
            for (int j = 0; j < 4; j++) sc[i][j] = 0.f;

        #pragma unroll
        for (int kk = 0; kk < 8; kk++) {
            #pragma unroll
            for (int ni = 0; ni < 8; ni++) {
                unsigned bf[2];
                bf[0] = Ks[st][ni * 8 + g][kk * 8 + t4];
                bf[1] = Ks[st][ni * 8 + g][kk * 8 + t4 + 4];
                mma8(sc[ni], aq[kk], bf);
            }
        }

        if (kt0 + KTILE > NTOK) {
            #pragma unroll
            for (int ni = 0; ni < 8; ni++) {
                int key = kt0 + ni * 8 + 2 * t4;
                if (key     >= NTOK) { sc[ni][0] = -1e30f; sc[ni][2] = -1e30f; }
                if (key + 1 >= NTOK) { sc[ni][1] = -1e30f; sc[ni][3] = -1e30f; }
            }
        }

        float mx0 = -1e30f, mx1 = -1e30f;
        #pragma unroll
        for (int ni = 0; ni < 8; ni++) {
            mx0 = fmaxf(mx0, fmaxf(sc[ni][0], sc[ni][1]));
            mx1 = fmaxf(mx1, fmaxf(sc[ni][2], sc[ni][3]));
        }
        mx0 = fmaxf(mx0, __shfl_xor_sync(0xffffffffu, mx0, 1));
        mx0 = fmaxf(mx0, __shfl_xor_sync(0xffffffffu, mx0, 2));
        mx1 = fmaxf(mx1, __shfl_xor_sync(0xffffffffu, mx1, 1));
        mx1 = fmaxf(mx1, __shfl_xor_sync(0xffffffffu, mx1, 2));
        float nm0 = fmaxf(m0, mx0), nm1 = fmaxf(m1, mx1);
        float cor0 = __expf(m0 - nm0), cor1 = __expf(m1 - nm1);
        m0 = nm0; m1 = nm1;

        float ps0 = 0.f, ps1 = 0.f;
        #pragma unroll
        for (int ni = 0; ni < 8; ni++) {
            sc[ni][0] = __expf(sc[ni][0] - nm0); ps0 += sc[ni][0];
            sc[ni][1] = __expf(sc[ni][1] - nm0); ps0 += sc[ni][1];
            sc[ni][2] = __expf(sc[ni][2] - nm1); ps1 += sc[ni][2];
            sc[ni][3] = __expf(sc[ni][3] - nm1); ps1 += sc[ni][3];
        }
        l0 = l0 * cor0 + ps0;
        l1 = l1 * cor1 + ps1;
        #pragma unroll
        for (int ni = 0; ni < 8; ni++) {
            o[ni][0] *= cor0; o[ni][1] *= cor0;
            o[ni][2] *= cor1; o[ni][3] *= cor1;
        }

        int srcA = (g << 2) | (t4 >> 1);
        int srcB = srcA + 2;
        bool hi = t4 & 1;
        #pragma unroll
        for (int kc = 0; kc < 8; kc++) {
            float v00 = __shfl_sync(0xffffffffu, sc[kc][0], srcA);
            float v01 = __shfl_sync(0xffffffffu, sc[kc][1], srcA);
            float v10 = __shfl_sync(0xffffffffu, sc[kc][2], srcA);
            float v11 = __shfl_sync(0xffffffffu, sc[kc][3], srcA);
            float w00 = __shfl_sync(0xffffffffu, sc[kc][0], srcB);
            float w01 = __shfl_sync(0xffffffffu, sc[kc][1], srcB);
            float w10 = __shfl_sync(0xffffffffu, sc[kc][2], srcB);
            float w11 = __shfl_sync(0xffffffffu, sc[kc][3], srcB);
            unsigned ap[4];
            ap[0] = f2tf(hi ? v01 : v00);
            ap[1] = f2tf(hi ? v11 : v10);
            ap[2] = f2tf(hi ? w01 : w00);
            ap[3] = f2tf(hi ? w11 : w10);
            #pragma unroll
            for (int ni = 0; ni < 8; ni++) {
                unsigned bf[2];
                bf[0] = Vs[st][kc * 8 + t4][ni * 8 + g];
                bf[1] = Vs[st][kc * 8 + t4 + 4][ni * 8 + g];
                mma8(o[ni], ap, bf);
            }
        }
    }

    l0 += __shfl_xor_sync(0xffffffffu, l0, 1);
    l0 += __shfl_xor_sync(0xffffffffu, l0, 2);
    l1 += __shfl_xor_sync(0xffffffffu, l1, 1);
    l1 += __shfl_xor_sync(0xffffffffu, l1, 2);
    float inv0 = 1.f / l0, inv1 = 1.f / l1;

    if (r0 < NTOK) {
        float* op = g_ao + ((size_t)b * NTOK + r0) * DIMC + h * DH;
        #pragma unroll
        for (int ni = 0; ni < 8; ni++)
            *(float2*)(op + ni * 8 + 2 * t4) =
                make_float2(tfr(o[ni][0] * inv0), tfr(o[ni][1] * inv0));
    }
    if (r1 < NTOK) {
        float* op = g_ao + ((size_t)b * NTOK + r1) * DIMC + h * DH;
        #pragma unroll
        for (int ni = 0; ni < 8; ni++)
            *(float2*)(op + ni * 8 + 2 * t4) =
                make_float2(tfr(o[ni][2] * inv1), tfr(o[ni][3] * inv1));
    }
}

// ---------------- launch ----------------
extern "C" void kernel_launch(void* const* d_in, const int* in_sizes, int n_in,
                              void* d_out, int out_size) {
    const float* x     = (const float*)d_in[0];
    const float* sinp  = (const float*)d_in[1];
    const float* cosp  = (const float*)d_in[2];
    const float* ln_g  = (const float*)d_in[3];
    const float* ln_b  = (const float*)d_in[4];
    const float* dw_w  = (const float*)d_in[5];
    const float* pw_w  = (const float*)d_in[6];
    const float* kv_w  = (const float*)d_in[7];
    const float* out_w = (const float*)d_in[8];
    const float* out_b = (const float*)d_in[9];
    float* out = (float*)d_out;

    float *p_dw, *p_pw, *p_xn, *p_kv, *p_ao, *p_pww, *p_kvw, *p_oww;
    cudaGetSymbolAddress((void**)&p_xn, g_xn);
    cudaGetSymbolAddress((void**)&p_dw, g_dw);
    cudaGetSymbolAddress((void**)&p_pw, g_pw);
    cudaGetSymbolAddress((void**)&p_kv, g_kv);
    cudaGetSymbolAddress((void**)&p_ao, g_ao);
    cudaGetSymbolAddress((void**)&p_pww, g_pww);
    cudaGetSymbolAddress((void**)&p_kvw, g_kvw);
    cudaGetSymbolAddress((void**)&p_oww, g_oww);

    // weight prep: pw round; kv/out transpose+round to [N][K]
    round_pw_kernel<<<(DIMC * DIMC + 255) / 256, 256>>>(pw_w);
    transpose_w_kernel<<<dim3(NKV / 32, DIMC / 32), dim3(32, 8)>>>(kv_w, p_kvw, DIMC, NKV);
    transpose_w_kernel<<<dim3(DIMC / 32, DIMC / 32), dim3(32, 8)>>>(out_w, p_oww, DIMC, DIMC);

    ln_kernel<<<BB * NTOK, 256>>>(x, ln_g, ln_b);
    dw_kernel2<<<dim3(DIMC / 16, 4, BB), 256>>>(dw_w);
    // pointwise conv: g_pw = g_dw @ pw_w^T    (M=8192, N=768, K=768)
    mma_gemm4<false><<<dim3(DIMC / 128, (BB * SP) / 128), 256>>>(
        p_dw, p_pww, nullptr, p_pw, BB * SP, DIMC, DIMC);
    // kv gemm: g_kv = g_xn @ kv_w             (M=8200, N=1536, K=768)
    mma_gemm4<false><<<dim3(NKV / 128, (BB * NTOK + 127) / 128), 256>>>(
        p_xn, p_kvw, nullptr, p_kv, BB * NTOK, NKV, DIMC);
    assemble_kernel<<<BB * NTOK, 256>>>(sinp, cosp);
    attn_mma_kernel<<<dim3(BB * HEADS, (NTOK + 127) / 128), 256>>>();
    // output projection + bias                (M=8200, N=768, K=768)
    mma_gemm4<true><<<dim3(DIMC / 128, (BB * NTOK + 127) / 128), 256>>>(
        p_ao, p_oww, out_b, out, BB * NTOK, DIMC, DIMC);
}

// round 9
// speedup vs baseline: 5.8718x; 1.7747x over previous
#include <cuda_runtime.h>
#include <cuda_fp16.h>
#include <math.h>

// ---------------- problem constants ----------------
#define BB    8
#define NTOK  1025
#define SP    1024
#define FHW   32
#define DIMC  768
#define NKV   1536
#define HEADS 12
#define DH    64
#define NROT  32

// ---------------- scratch ----------------
__device__ __half g_xn[BB*NTOK*DIMC];     // layernorm out (half)
__device__ __half g_dw[BB*SP*DIMC];       // depthwise out (half)
__device__ float  g_pw[BB*SP*DIMC];       // pointwise out (fp32, feeds rope)
__device__ float  g_kv[BB*NTOK*NKV];      // kv gemm out (fp32, feeds rope)
__device__ __half g_q [BB*NTOK*DIMC];
__device__ __half g_k [BB*NTOK*DIMC];
__device__ __half g_v [BB*NTOK*DIMC];
__device__ __half g_ao[BB*NTOK*DIMC];     // attention out (half)
__device__ __half g_pww[DIMC*DIMC];       // [N][K] half
__device__ __half g_kvw[NKV*DIMC];        // [N][K] half (transposed)
__device__ __half g_oww[DIMC*DIMC];       // [N][K] half (transposed)

// ---------------- helpers ----------------
__device__ __forceinline__ void mma16(float* c, const unsigned* a, const unsigned* b) {
    asm volatile(
        "mma.sync.aligned.m16n8k16.row.col.f32.f16.f16.f32 "
        "{%0,%1,%2,%3}, {%4,%5,%6,%7}, {%8,%9}, {%0,%1,%2,%3};"
        : "+f"(c[0]), "+f"(c[1]), "+f"(c[2]), "+f"(c[3])
        : "r"(a[0]), "r"(a[1]), "r"(a[2]), "r"(a[3]), "r"(b[0]), "r"(b[1]));
}
__device__ __forceinline__ void cp16(void* dst, const void* src, bool valid) {
    unsigned d = (unsigned)__cvta_generic_to_shared(dst);
    int sz = valid ? 16 : 0;
    asm volatile("cp.async.ca.shared.global [%0], [%1], 16, %2;\n"
                 :: "r"(d), "l"(src), "r"(sz));
}
__device__ __forceinline__ void cp_commit() {
    asm volatile("cp.async.commit_group;\n");
}
template<int N>
__device__ __forceinline__ void cp_waitg() {
    asm volatile("cp.async.wait_group %0;\n" :: "n"(N));
}
__device__ __forceinline__ void ldsm4t(unsigned& r0, unsigned& r1,
                                       unsigned& r2, unsigned& r3, const void* p) {
    unsigned a = (unsigned)__cvta_generic_to_shared(p);
    asm volatile("ldmatrix.sync.aligned.m8n8.x4.trans.shared.b16 {%0,%1,%2,%3}, [%4];"
                 : "=r"(r0), "=r"(r1), "=r"(r2), "=r"(r3) : "r"(a));
}
__device__ __forceinline__ unsigned packh2(float lo, float hi) {
    __half2 h = __floats2half2_rn(lo, hi);
    return *reinterpret_cast<unsigned*>(&h);
}

// ---------------- weight prep ----------------
__global__ void round_pw_kernel(const float* __restrict__ pw) {
    int i = blockIdx.x * 256 + threadIdx.x;
    if (i < DIMC*DIMC) g_pww[i] = __float2half_rn(pw[i]);
}
// src: [K][N] fp32 -> dst: [N][K] half
__global__ void transpose_w_kernel(const float* __restrict__ src,
                                   __half* __restrict__ dst, int K, int N) {
    __shared__ float tile[32][33];
    int n0 = blockIdx.x * 32, k0 = blockIdx.y * 32;
    int tx = threadIdx.x, ty = threadIdx.y;
    #pragma unroll
    for (int dy = ty; dy < 32; dy += 8)
        tile[dy][tx] = src[(size_t)(k0 + dy) * N + n0 + tx];
    __syncthreads();
    #pragma unroll
    for (int dy = ty; dy < 32; dy += 8)
        dst[(size_t)(n0 + dy) * K + k0 + tx] = __float2half_rn(tile[tx][dy]);
}

// ---------------- layernorm (half output) ----------------
__global__ void ln_kernel(const float* __restrict__ x,
                          const float* __restrict__ gamma,
                          const float* __restrict__ beta) {
    int row = blockIdx.x;
    int t = threadIdx.x;
    const float* xr = x + (size_t)row * DIMC;

    float v0 = xr[t], v1 = xr[t + 256], v2 = xr[t + 512];
    float s  = v0 + v1 + v2;
    float s2 = v0*v0 + v1*v1 + v2*v2;

    int lane = t & 31, w = t >> 5;
    #pragma unroll
    for (int o = 16; o; o >>= 1) {
        s  += __shfl_xor_sync(0xffffffffu, s,  o);
        s2 += __shfl_xor_sync(0xffffffffu, s2, o);
    }
    __shared__ float shs[8], shs2[8];
    if (lane == 0) { shs[w] = s; shs2[w] = s2; }
    __syncthreads();
    if (w == 0) {
        float a  = (lane < 8) ? shs[lane]  : 0.f;
        float a2 = (lane < 8) ? shs2[lane] : 0.f;
        #pragma unroll
        for (int o = 4; o; o >>= 1) {
            a  += __shfl_xor_sync(0xffffffffu, a,  o);
            a2 += __shfl_xor_sync(0xffffffffu, a2, o);
        }
        if (lane == 0) { shs[0] = a; shs2[0] = a2; }
    }
    __syncthreads();
    float mu  = shs[0] * (1.f / DIMC);
    float var = shs2[0] * (1.f / DIMC) - mu * mu;
    float r = rsqrtf(var + 1e-5f);

    __half* o = g_xn + (size_t)row * DIMC;
    o[t]       = __float2half_rn((v0 - mu) * r * gamma[t]       + beta[t]);
    o[t + 256] = __float2half_rn((v1 - mu) * r * gamma[t + 256] + beta[t + 256]);
    o[t + 512] = __float2half_rn((v2 - mu) * r * gamma[t + 512] + beta[t + 512]);
}

// ---------------- depthwise 5x5 conv, smem-tiled (half in/out) -------------
__global__ void __launch_bounds__(256) dw_kernel2(const float* __restrict__ w) {
    __shared__ float S[12][36][16];
    __shared__ float Ws[16][25];
    int c0 = blockIdx.x * 16;
    int y0 = blockIdx.y * 8;
    int b  = blockIdx.z;
    int tid = threadIdx.x;
    const __half* xn_b = g_xn + ((size_t)b * NTOK + 1) * DIMC;

    for (int i = tid; i < 16 * 25; i += 256) {
        int c = i / 25, kk = i % 25;
        Ws[c][kk] = w[(c0 + c) * 25 + kk];
    }
    for (int i = tid; i < 12 * 36 * 16; i += 256) {
        int row = i / 576, rem = i % 576;
        int col = rem / 16, ch = rem % 16;
        int gy = y0 + row - 2, gx = col - 2;
        float v = 0.f;
        if (gy >= 0 && gy < FHW && gx >= 0 && gx < FHW)
            v = __half2float(xn_b[(size_t)(gy * 32 + gx) * DIMC + c0 + ch]);
        S[row][col][ch] = v;
    }
    __syncthreads();

    for (int k = 0; k < 16; k++) {
        int oi = k * 256 + tid;
        int oc = oi & 15;
        int ox = (oi >> 4) & 31;
        int oy = oi >> 9;
        float acc = 0.f;
        #pragma unroll
        for (int ky = 0; ky < 5; ky++)
            #pragma unroll
            for (int kx = 0; kx < 5; kx++)
                acc = fmaf(Ws[oc][ky * 5 + kx], S[oy + ky][ox + kx][oc], acc);
        g_dw[((size_t)b * SP + (y0 + oy) * 32 + ox) * DIMC + c0 + oc] = __float2half_rn(acc);
    }
}

// ---------------- fp16 MMA GEMM: C[M,N] = A[M,K] @ B^T (+bias) -------------
// A [M][K] half, B [N][K] half. K%32==0, N%128==0.
// k-relabel inside each k16 block: slots (2t4,2t4+1,2t4+8,2t4+9) <- phys 4t4..4t4+3.
// XOR-16-half swizzle on rows with (row&2) keeps 32-half rows conflict-free.
template<bool HAS_BIAS>
__global__ void __launch_bounds__(256, 2)
hgemm(const __half* __restrict__ A, const __half* __restrict__ B,
      const float* __restrict__ bias, float* __restrict__ C,
      int M, int N, int K) {
    __shared__ __align__(16) __half As[2][128][32];
    __shared__ __align__(16) __half Bs[2][128][32];

    int tid = threadIdx.x;
    int lane = tid & 31, warp = tid >> 5;
    int wm = warp >> 2, wn = warp & 3;
    int g = lane >> 2, t4 = lane & 3;
    int bm = blockIdx.y * 128, bn = blockIdx.x * 128;

    int ar = tid >> 1, ak = (tid & 1) * 16;
    int asw = (ar & 2) ? 16 : 0;

    auto issue = [&](int st, int k0) {
        const __half* ga = A + (size_t)(bm + ar) * K + k0 + ak;
        bool av = (bm + ar) < M;
        cp16(&As[st][ar][ak ^ asw],       ga,     av);
        cp16(&As[st][ar][(ak + 8) ^ asw], ga + 8, av);
        const __half* gb = B + (size_t)(bn + ar) * K + k0 + ak;
        cp16(&Bs[st][ar][ak ^ asw],       gb,     true);
        cp16(&Bs[st][ar][(ak + 8) ^ asw], gb + 8, true);
    };

    float acc[4][4][4];
    #pragma unroll
    for (int i = 0; i < 4; i++)
        #pragma unroll
        for (int j = 0; j < 4; j++)
            #pragma unroll
            for (int r = 0; r < 4; r++) acc[i][j][r] = 0.f;

    issue(0, 0);
    cp_commit();

    int fsw = (g & 2) ? 16 : 0;     // frag-read swizzle (row&2 == g&2 in all uses)
    int NT = K >> 5;
    for (int t = 0; t < NT; t++) {
        if (t > 0) __syncthreads();
        if (t + 1 < NT) issue((t + 1) & 1, (t + 1) * 32);
        cp_commit();
        cp_waitg<1>();
        __syncthreads();
        int cur = t & 1;

        #pragma unroll
        for (int kb = 0; kb < 2; kb++) {
            int kc = (kb * 16 + 4 * t4) ^ fsw;
            unsigned af[4][4], bf[4][2];
            #pragma unroll
            for (int mi = 0; mi < 4; mi++) {
                int m0 = wm * 64 + mi * 16 + g;
                uint2 alo = *(const uint2*)&As[cur][m0][kc];
                uint2 ahi = *(const uint2*)&As[cur][m0 + 8][kc];
                af[mi][0] = alo.x; af[mi][1] = ahi.x;
                af[mi][2] = alo.y; af[mi][3] = ahi.y;
            }
            #pragma unroll
            for (int ni = 0; ni < 4; ni++) {
                int n0 = wn * 32 + ni * 8 + g;
                uint2 bb = *(const uint2*)&Bs[cur][n0][kc];
                bf[ni][0] = bb.x; bf[ni][1] = bb.y;
            }
            #pragma unroll
            for (int mi = 0; mi < 4; mi++)
                #pragma unroll
                for (int ni = 0; ni < 4; ni++)
                    mma16(acc[mi][ni], af[mi], bf[ni]);
        }
    }

    #pragma unroll
    for (int mi = 0; mi < 4; mi++) {
        int row0 = bm + wm * 64 + mi * 16 + g;
        int row1 = row0 + 8;
        #pragma unroll
        for (int ni = 0; ni < 4; ni++) {
            int col = bn + wn * 32 + ni * 8 + 2 * t4;
            float b0 = 0.f, b1 = 0.f;
            if (HAS_BIAS) { b0 = bias[col]; b1 = bias[col + 1]; }
            if (row0 < M) {
                float2 v = make_float2(acc[mi][ni][0] + b0, acc[mi][ni][1] + b1);
                *(float2*)(C + (size_t)row0 * N + col) = v;
            }
            if (row1 < M) {
                float2 v = make_float2(acc[mi][ni][2] + b0, acc[mi][ni][3] + b1);
                *(float2*)(C + (size_t)row1 * N + col) = v;
            }
        }
    }
}

// ---------------- q assembly + rope + kv split (half outputs) ---------------
__global__ void assemble_kernel(const float* __restrict__ sinp,
                                const float* __restrict__ cosp) {
    int row = blockIdx.x;
    int b = row / NTOK, n = row % NTOK;
    const float* pwrow = (n > 0) ? (g_pw + ((size_t)b * SP + (n - 1)) * DIMC) : nullptr;
    const float* kvrow = g_kv + (size_t)row * NKV;
    const __half* xnrow = g_xn + (size_t)row * DIMC;
    int pos = n - 1;

    for (int c = threadIdx.x; c < DIMC; c += 256) {
        float qv, kv_;
        float vv = kvrow[DIMC + c];
        kv_ = kvrow[c];
        if (n == 0) {
            qv = __half2float(xnrow[c]);
        } else {
            qv = pwrow[c];
            int d = c & 63;
            if (d < NROT) {
                float cs = cosp[pos * NROT + d];
                float sn = sinp[pos * NROT + d];
                float qpart = pwrow[c ^ 1];
                float kpart = kvrow[c ^ 1];
                float qrot = (d & 1) ? qpart : -qpart;
                float krot = (d & 1) ? kpart : -kpart;
                qv  = qv  * cs + qrot * sn;
                kv_ = kv_ * cs + krot * sn;
            }
        }
        g_q[(size_t)row * DIMC + c] = __float2half_rn(qv);
        g_k[(size_t)row * DIMC + c] = __float2half_rn(kv_);
        g_v[(size_t)row * DIMC + c] = __float2half_rn(vv);
    }
}

// ---------------- fp16 tensor-core flash attention --------------------------
// block 256 (8 warps) x 128 queries of one (b,h); key tiles of 64.
// S: m16n8k16 with k-relabel on Q/K. PV: S C-frag == PV A-frag (pack only),
// V B-frags via ldmatrix.x4.trans.
#define KTILE 64
#define KSTRH 80   // Ks stride (halves): 40-word rows -> conflict-free uint2 frags
#define VSTRH 72   // Vs stride (halves): 36-word rows -> conflict-free ldmatrix

__global__ void __launch_bounds__(256, 2)
attn_mma_kernel() {
    __shared__ __align__(16) __half Ks[2][KTILE][KSTRH];
    __shared__ __align__(16) __half Vs[2][KTILE][VSTRH];

    int bh = blockIdx.x;
    int b = bh / HEADS, h = bh % HEADS;
    int qt0 = blockIdx.y * 128;
    int tid = threadIdx.x, lane = tid & 31, warp = tid >> 5;
    int g = lane >> 2, t4 = lane & 3;

    const __half* qb = g_q + ((size_t)b * NTOK) * DIMC + h * DH;
    const __half* kb = g_k + ((size_t)b * NTOK) * DIMC + h * DH;
    const __half* vb = g_v + ((size_t)b * NTOK) * DIMC + h * DH;

    int r0 = qt0 + warp * 16 + g;
    int r1 = r0 + 8;

    auto issue_kv = [&](int st, int kt0) {
        #pragma unroll
        for (int lp = 0; lp < 4; lp++) {
            int pos = tid + lp * 256;         // 0..1023
            int mat = pos >> 9;               // 0=K, 1=V
            int idx = pos & 511;
            int row = idx >> 3, seg = idx & 7;
            int key = kt0 + row;
            bool vld = key < NTOK;
            const __half* src = (mat ? vb : kb) + (size_t)key * DIMC + seg * 8;
            if (mat == 0) cp16(&Ks[st][row][seg * 8], src, vld);
            else          cp16(&Vs[st][row][seg * 8], src, vld);
        }
    };

    // Q A-frags (raw, unscaled; scale folded into exp2 constant)
    unsigned aq[4][4];
    #pragma unroll
    for (int kbk = 0; kbk < 4; kbk++) {
        uint2 lo = make_uint2(0u, 0u), hi = make_uint2(0u, 0u);
        if (r0 < NTOK) lo = *(const uint2*)(qb + (size_t)r0 * DIMC + kbk * 16 + 4 * t4);
        if (r1 < NTOK) hi = *(const uint2*)(qb + (size_t)r1 * DIMC + kbk * 16 + 4 * t4);
        aq[kbk][0] = lo.x; aq[kbk][1] = hi.x;
        aq[kbk][2] = lo.y; aq[kbk][3] = hi.y;
    }

    float o[8][4];
    #pragma unroll
    for (int i = 0; i < 8; i++)
        #pragma unroll
        for (int j = 0; j < 4; j++) o[i][j] = 0.f;
    float m0 = -1e30f, m1 = -1e30f, l0 = 0.f, l1 = 0.f;
    const float CEXP = 0.18033688011112042f;   // 0.125 * log2(e)

    issue_kv(0, 0);
    cp_commit();

    const int NTILES = (NTOK + KTILE - 1) / KTILE;
    for (int it = 0; it < NTILES; it++) {
        __syncthreads();
        if (it + 1 < NTILES) issue_kv((it + 1) & 1, (it + 1) * KTILE);
        cp_commit();
        cp_waitg<1>();
        __syncthreads();
        int st = it & 1;
        int kt0 = it * KTILE;

        // ---- S = Q K^T (raw scores) ----
        float sc[8][4];
        #pragma unroll
        for (int i = 0; i < 8; i++)
            #pragma unroll
            for (int j = 0; j < 4; j++) sc[i][j] = 0.f;

        #pragma unroll
        for (int kbk = 0; kbk < 4; kbk++) {
            #pragma unroll
            for (int ni = 0; ni < 8; ni++) {
                uint2 bb = *(const uint2*)&Ks[st][ni * 8 + g][kbk * 16 + 4 * t4];
                unsigned bf[2] = {bb.x, bb.y};
                mma16(sc[ni], aq[kbk], bf);
            }
        }

        if (kt0 + KTILE > NTOK) {
            #pragma unroll
            for (int ni = 0; ni < 8; ni++) {
                int key = kt0 + ni * 8 + 2 * t4;
                if (key     >= NTOK) { sc[ni][0] = -1e30f; sc[ni][2] = -1e30f; }
                if (key + 1 >= NTOK) { sc[ni][1] = -1e30f; sc[ni][3] = -1e30f; }
            }
        }

        // ---- online softmax (raw-score max, exp2 with folded scale) ----
        float mx0 = -1e30f, mx1 = -1e30f;
        #pragma unroll
        for (int ni = 0; ni < 8; ni++) {
            mx0 = fmaxf(mx0, fmaxf(sc[ni][0], sc[ni][1]));
            mx1 = fmaxf(mx1, fmaxf(sc[ni][2], sc[ni][3]));
        }
        mx0 = fmaxf(mx0, __shfl_xor_sync(0xffffffffu, mx0, 1));
        mx0 = fmaxf(mx0, __shfl_xor_sync(0xffffffffu, mx0, 2));
        mx1 = fmaxf(mx1, __shfl_xor_sync(0xffffffffu, mx1, 1));
        mx1 = fmaxf(mx1, __shfl_xor_sync(0xffffffffu, mx1, 2));
        float nm0 = fmaxf(m0, mx0), nm1 = fmaxf(m1, mx1);
        float cor0 = exp2f((m0 - nm0) * CEXP), cor1 = exp2f((m1 - nm1) * CEXP);
        m0 = nm0; m1 = nm1;
        float mc0 = nm0 * CEXP, mc1 = nm1 * CEXP;

        float ps0 = 0.f, ps1 = 0.f;
        #pragma unroll
        for (int ni = 0; ni < 8; ni++) {
            sc[ni][0] = exp2f(fmaf(sc[ni][0], CEXP, -mc0)); ps0 += sc[ni][0];
            sc[ni][1] = exp2f(fmaf(sc[ni][1], CEXP, -mc0)); ps0 += sc[ni][1];
            sc[ni][2] = exp2f(fmaf(sc[ni][2], CEXP, -mc1)); ps1 += sc[ni][2];
            sc[ni][3] = exp2f(fmaf(sc[ni][3], CEXP, -mc1)); ps1 += sc[ni][3];
        }
        l0 = l0 * cor0 + ps0;
        l1 = l1 * cor1 + ps1;
        #pragma unroll
        for (int ni = 0; ni < 8; ni++) {
            o[ni][0] *= cor0; o[ni][1] *= cor0;
            o[ni][2] *= cor1; o[ni][3] *= cor1;
        }

        // ---- O += P V : pack C-frag -> A-frag, V via ldmatrix.x4.trans ----
        int vmat = lane >> 3, vr = lane & 7;
        #pragma unroll
        for (int kc = 0; kc < 4; kc++) {
            unsigned ap[4];
            ap[0] = packh2(sc[2*kc][0],     sc[2*kc][1]);
            ap[1] = packh2(sc[2*kc][2],     sc[2*kc][3]);
            ap[2] = packh2(sc[2*kc+1][0],   sc[2*kc+1][1]);
            ap[3] = packh2(sc[2*kc+1][2],   sc[2*kc+1][3]);
            #pragma unroll
            for (int np = 0; np < 4; np++) {   // n-block pairs (16 d-cols each)
                unsigned b0, b1, b2, b3;
                const __half* vp = &Vs[st][kc * 16 + (vmat & 1) * 8 + vr]
                                      [np * 16 + (vmat >> 1) * 8];
                ldsm4t(b0, b1, b2, b3, vp);
                unsigned bfa[2] = {b0, b1}, bfb[2] = {b2, b3};
                mma16(o[np * 2],     ap, bfa);
                mma16(o[np * 2 + 1], ap, bfb);
            }
        }
    }

    l0 += __shfl_xor_sync(0xffffffffu, l0, 1);
    l0 += __shfl_xor_sync(0xffffffffu, l0, 2);
    l1 += __shfl_xor_sync(0xffffffffu, l1, 1);
    l1 += __shfl_xor_sync(0xffffffffu, l1, 2);
    float inv0 = 1.f / l0, inv1 = 1.f / l1;

    if (r0 < NTOK) {
        __half* op = g_ao + ((size_t)b * NTOK + r0) * DIMC + h * DH;
        #pragma unroll
        for (int ni = 0; ni < 8; ni++)
            *(unsigned*)(op + ni * 8 + 2 * t4) = packh2(o[ni][0] * inv0, o[ni][1] * inv0);
    }
    if (r1 < NTOK) {
        __half* op = g_ao + ((size_t)b * NTOK + r1) * DIMC + h * DH;
        #pragma unroll
        for (int ni = 0; ni < 8; ni++)
            *(unsigned*)(op + ni * 8 + 2 * t4) = packh2(o[ni][2] * inv1, o[ni][3] * inv1);
    }
}

// ---------------- launch ----------------
extern "C" void kernel_launch(void* const* d_in, const int* in_sizes, int n_in,
                              void* d_out, int out_size) {
    const float* x     = (const float*)d_in[0];
    const float* sinp  = (const float*)d_in[1];
    const float* cosp  = (const float*)d_in[2];
    const float* ln_g  = (const float*)d_in[3];
    const float* ln_b  = (const float*)d_in[4];
    const float* dw_w  = (const float*)d_in[5];
    const float* pw_w  = (const float*)d_in[6];
    const float* kv_w  = (const float*)d_in[7];
    const float* out_w = (const float*)d_in[8];
    const float* out_b = (const float*)d_in[9];
    float* out = (float*)d_out;

    __half *p_dwh, *p_xnh, *p_aoh, *p_pww, *p_kvw, *p_oww;
    float *p_pw, *p_kv;
    cudaGetSymbolAddress((void**)&p_xnh, g_xn);
    cudaGetSymbolAddress((void**)&p_dwh, g_dw);
    cudaGetSymbolAddress((void**)&p_pw,  g_pw);
    cudaGetSymbolAddress((void**)&p_kv,  g_kv);
    cudaGetSymbolAddress((void**)&p_aoh, g_ao);
    cudaGetSymbolAddress((void**)&p_pww, g_pww);
    cudaGetSymbolAddress((void**)&p_kvw, g_kvw);
    cudaGetSymbolAddress((void**)&p_oww, g_oww);

    round_pw_kernel<<<(DIMC * DIMC + 255) / 256, 256>>>(pw_w);
    transpose_w_kernel<<<dim3(NKV / 32, DIMC / 32), dim3(32, 8)>>>(kv_w, p_kvw, DIMC, NKV);
    transpose_w_kernel<<<dim3(DIMC / 32, DIMC / 32), dim3(32, 8)>>>(out_w, p_oww, DIMC, DIMC);

    ln_kernel<<<BB * NTOK, 256>>>(x, ln_g, ln_b);
    dw_kernel2<<<dim3(DIMC / 16, 4, BB), 256>>>(dw_w);
    // pointwise conv: g_pw = g_dw @ pw_w^T    (M=8192, N=768, K=768)
    hgemm<false><<<dim3(DIMC / 128, (BB * SP) / 128), 256>>>(
        p_dwh, p_pww, nullptr, p_pw, BB * SP, DIMC, DIMC);
    // kv gemm: g_kv = g_xn @ kv_w             (M=8200, N=1536, K=768)
    hgemm<false><<<dim3(NKV / 128, (BB * NTOK + 127) / 128), 256>>>(
        p_xnh, p_kvw, nullptr, p_kv, BB * NTOK, NKV, DIMC);
    assemble_kernel<<<BB * NTOK, 256>>>(sinp, cosp);
    attn_mma_kernel<<<dim3(BB * HEADS, (NTOK + 127) / 128), 256>>>();
    // output projection + bias                (M=8200, N=768, K=768)
    hgemm<true><<<dim3(DIMC / 128, (BB * NTOK + 127) / 128), 256>>>(
        p_aoh, p_oww, out_b, out, BB * NTOK, DIMC, DIMC);
}